// round 1
// baseline (speedup 1.0000x reference)
#include <cuda_runtime.h>
#include <math.h>

// Problem constants
// B=2, S=1024, E=2560, H=32, D=80, 3E=7680, BS=2048

__device__ float g_qkv[2048ull * 7680];   // (B*S, 3E)
__device__ float g_attn[2048ull * 2560];  // (B*S, E) pre-projection

// ---------------------------------------------------------------------------
// Classic 128x128x8 register-tiled SGEMM: C = A @ B + bias(broadcast over rows)
// A: (M,K) row-major, B: (K,N) row-major, C: (M,N). M%128==0, N%128==0, K%8==0.
// ---------------------------------------------------------------------------
__global__ __launch_bounds__(256) void sgemm128(
    const float* __restrict__ A, const float* __restrict__ Bm,
    const float* __restrict__ bias, float* __restrict__ C,
    int M, int N, int K)
{
    __shared__ float As[8][128];
    __shared__ float Bs[8][128];

    const int tid = threadIdx.x;
    const int bx = blockIdx.x, by = blockIdx.y;

    const int aRow = tid >> 1;           // 0..127
    const int aCol = (tid & 1) << 2;     // 0 or 4
    const int bRow = tid >> 5;           // 0..7
    const int bCol = (tid & 31) << 2;    // 0..124

    const float* Aptr = A + (size_t)(by * 128 + aRow) * K + aCol;
    const float* Bptr = Bm + (size_t)bRow * N + bx * 128 + bCol;

    const int ty = (tid >> 4) << 3;      // 0..120
    const int tx = (tid & 15) << 3;      // 0..120

    float acc[8][8];
#pragma unroll
    for (int i = 0; i < 8; i++)
#pragma unroll
        for (int j = 0; j < 8; j++) acc[i][j] = 0.0f;

    for (int kt = 0; kt < K; kt += 8) {
        float4 a = *(const float4*)(Aptr + kt);
        float4 b = *(const float4*)(Bptr + (size_t)kt * N);
        __syncthreads();
        As[aCol + 0][aRow] = a.x;
        As[aCol + 1][aRow] = a.y;
        As[aCol + 2][aRow] = a.z;
        As[aCol + 3][aRow] = a.w;
        *(float4*)&Bs[bRow][bCol] = b;
        __syncthreads();

#pragma unroll
        for (int k = 0; k < 8; k++) {
            float rm[8], rn[8];
            *(float4*)&rm[0] = *(const float4*)&As[k][ty];
            *(float4*)&rm[4] = *(const float4*)&As[k][ty + 4];
            *(float4*)&rn[0] = *(const float4*)&Bs[k][tx];
            *(float4*)&rn[4] = *(const float4*)&Bs[k][tx + 4];
#pragma unroll
            for (int i = 0; i < 8; i++)
#pragma unroll
                for (int j = 0; j < 8; j++)
                    acc[i][j] += rm[i] * rn[j];
        }
    }

    float bv[8];
#pragma unroll
    for (int j = 0; j < 8; j++) bv[j] = bias[bx * 128 + tx + j];

#pragma unroll
    for (int i = 0; i < 8; i++) {
        float4 o0 = make_float4(acc[i][0] + bv[0], acc[i][1] + bv[1],
                                acc[i][2] + bv[2], acc[i][3] + bv[3]);
        float4 o1 = make_float4(acc[i][4] + bv[4], acc[i][5] + bv[5],
                                acc[i][6] + bv[6], acc[i][7] + bv[7]);
        float* cp = C + (size_t)(by * 128 + ty + i) * N + bx * 128 + tx;
        *(float4*)cp = o0;
        *(float4*)(cp + 4) = o1;
    }
}

// ---------------------------------------------------------------------------
// Fused quantum attention per (b,h) and 16-query-row tile.
// Scores (4 variants) -> interference combine -> softmax -> *cos(phase) -> P@V
// SMEM (floats): coeff[240] | row_l[16] | qs[4*16*80] | ks[128*81] | sc[16*1040]
// = 32384 floats = 129536 bytes (dynamic).
// ---------------------------------------------------------------------------
__global__ __launch_bounds__(256) void attn_kernel(
    const float* __restrict__ qkv,
    const float* __restrict__ gm,   // gate_mats (3,2,2)
    const float* __restrict__ gp,   // gate_phases (3,80)
    const float* __restrict__ ga,   // gate_amps (3,80)
    const float* __restrict__ qp,   // quantum_phase (32)
    const float* __restrict__ isr,  // interference_strength scalar
    float* __restrict__ attn_out)
{
    extern __shared__ float sm[];
    float* coeff = sm;            // 240
    float* row_l = sm + 240;      // 16
    float* qs    = sm + 256;      // 5120  : [g][r][d], g in {plain,c0,c1,c2}
    float* ks    = sm + 5376;     // 10368 : [key][81] padded rows (k or v tile)
    float* sc    = sm + 15744;    // 16640 : [r][1040] padded score rows

    const int tid  = threadIdx.x;
    const int warp = tid >> 5, lane = tid & 31;
    const int bh = blockIdx.y;
    const int b = bh >> 5, h = bh & 31;
    const int qt = blockIdx.x;    // query tile: rows qt*16 .. qt*16+15

    // gate coefficients: (cos(p)*(g00+g01) + sin(p)*(g10+g11)) * amp
    if (tid < 240) {
        int g = tid / 80, d = tid - g * 80;
        float r0 = gm[g * 4 + 0] + gm[g * 4 + 1];
        float r1 = gm[g * 4 + 2] + gm[g * 4 + 3];
        float ph = gp[g * 80 + d];
        coeff[tid] = (cosf(ph) * r0 + sinf(ph) * r1) * ga[g * 80 + d];
    }
    __syncthreads();

    // load 16 q rows + 3 coeff-scaled copies
    const float* qbase = qkv + (size_t)(b * 1024 + qt * 16) * 7680 + h * 80;
    for (int i = tid; i < 1280; i += 256) {
        int r = i / 80, d = i - r * 80;
        float v = qbase[(size_t)r * 7680 + d];
        qs[i]        = v;
        qs[1280 + i] = v * coeff[d];
        qs[2560 + i] = v * coeff[80 + d];
        qs[3840 + i] = v * coeff[160 + d];
    }

    const float scale = rsqrtf(80.0f);
    const float intf  = isr[0] * (1.0f / 3.0f);
    const float* kbase = qkv + (size_t)(b * 1024) * 7680 + 2560 + h * 80;
    const int r0 = warp * 2;

    // ---- Phase 1: scores (all 1024 keys, 8 tiles of 128) ----
    for (int kt = 0; kt < 8; kt++) {
        __syncthreads();
        for (int i = tid; i < 2560; i += 256) {
            int key = i / 20, db = (i - key * 20) * 4;
            float4 f = *(const float4*)(kbase + (size_t)(kt * 128 + key) * 7680 + db);
            int o = key * 81 + db;
            ks[o] = f.x; ks[o + 1] = f.y; ks[o + 2] = f.z; ks[o + 3] = f.w;
        }
        __syncthreads();

        float acc[2][4][4];
#pragma unroll
        for (int m = 0; m < 2; m++)
#pragma unroll
            for (int g = 0; g < 4; g++)
#pragma unroll
                for (int n = 0; n < 4; n++) acc[m][g][n] = 0.0f;

        const float* q0 = qs + r0 * 80;
#pragma unroll 4
        for (int d = 0; d < 80; d++) {
            float kv0 = ks[lane * 81 + d];
            float kv1 = ks[(lane + 32) * 81 + d];
            float kv2 = ks[(lane + 64) * 81 + d];
            float kv3 = ks[(lane + 96) * 81 + d];
#pragma unroll
            for (int m = 0; m < 2; m++) {
#pragma unroll
                for (int g = 0; g < 4; g++) {
                    float qv = q0[g * 1280 + m * 80 + d];
                    acc[m][g][0] += qv * kv0;
                    acc[m][g][1] += qv * kv1;
                    acc[m][g][2] += qv * kv2;
                    acc[m][g][3] += qv * kv3;
                }
            }
        }

#pragma unroll
        for (int m = 0; m < 2; m++) {
            float* srow = sc + (r0 + m) * 1040 + kt * 128 + lane;
#pragma unroll
            for (int n = 0; n < 4; n++) {
                float s  = acc[m][0][n] * scale;
                float a0 = acc[m][1][n] * scale;
                float a1 = acc[m][2][n] * scale;
                float a2 = acc[m][3][n] * scale;
                srow[n * 32] = s + (a0 * a1 + a0 * a2 + a1 * a2) * intf;
            }
        }
    }
    __syncthreads();

    // ---- Phase 2: softmax (warp w owns rows 2w, 2w+1), store exp, keep rowsum ----
#pragma unroll
    for (int rr = 0; rr < 2; rr++) {
        int r = r0 + rr;
        float* row = sc + r * 1040;
        float mx = -1e30f;
#pragma unroll 8
        for (int j = 0; j < 32; j++) mx = fmaxf(mx, row[lane + j * 32]);
#pragma unroll
        for (int off = 16; off > 0; off >>= 1)
            mx = fmaxf(mx, __shfl_xor_sync(0xffffffffu, mx, off));
        float sum = 0.0f;
#pragma unroll 8
        for (int j = 0; j < 32; j++) {
            float p = __expf(row[lane + j * 32] - mx);
            row[lane + j * 32] = p;
            sum += p;
        }
#pragma unroll
        for (int off = 16; off > 0; off >>= 1)
            sum += __shfl_xor_sync(0xffffffffu, sum, off);
        if (lane == 0) row_l[r] = sum;
    }

    // ---- Phase 3: P @ V. thread -> (row = tid/16, 5 d-cols) ----
    const int pr = tid >> 4;
    const int d0 = (tid & 15) * 5;
    float pacc[5] = {0, 0, 0, 0, 0};
    const float* vbase = qkv + (size_t)(b * 1024) * 7680 + 5120 + h * 80;

    for (int kt = 0; kt < 8; kt++) {
        __syncthreads();
        for (int i = tid; i < 2560; i += 256) {
            int key = i / 20, db = (i - key * 20) * 4;
            float4 f = *(const float4*)(vbase + (size_t)(kt * 128 + key) * 7680 + db);
            int o = key * 81 + db;
            ks[o] = f.x; ks[o + 1] = f.y; ks[o + 2] = f.z; ks[o + 3] = f.w;
        }
        __syncthreads();
        const float* prow = sc + pr * 1040 + kt * 128;
#pragma unroll 4
        for (int k = 0; k < 128; k++) {
            float p = prow[k];
            const float* vv = ks + k * 81 + d0;
#pragma unroll
            for (int j = 0; j < 5; j++) pacc[j] += p * vv[j];
        }
    }

    float fac = cosf(qp[h]) / row_l[pr];
    float* ob = attn_out + (size_t)(b * 1024 + qt * 16 + pr) * 2560 + h * 80 + d0;
#pragma unroll
    for (int j = 0; j < 5; j++) ob[j] = pacc[j] * fac;
}

// ---------------------------------------------------------------------------
extern "C" void kernel_launch(void* const* d_in, const int* in_sizes, int n_in,
                              void* d_out, int out_size)
{
    const float* hidden = (const float*)d_in[0];
    const float* Wqkv   = (const float*)d_in[1];
    const float* bqkv   = (const float*)d_in[2];
    const float* Wproj  = (const float*)d_in[3];
    const float* bproj  = (const float*)d_in[4];
    const float* gm     = (const float*)d_in[5];
    const float* gp     = (const float*)d_in[6];
    const float* ga     = (const float*)d_in[7];
    const float* qp     = (const float*)d_in[8];
    const float* isr    = (const float*)d_in[9];
    float* out = (float*)d_out;

    void* qkvp = nullptr;
    void* attnp = nullptr;
    cudaGetSymbolAddress(&qkvp, g_qkv);
    cudaGetSymbolAddress(&attnp, g_attn);
    float* qkv = (float*)qkvp;
    float* attn = (float*)attnp;

    const int SMEM_BYTES = 32384 * 4;  // 129536
    cudaFuncSetAttribute(attn_kernel,
                         cudaFuncAttributeMaxDynamicSharedMemorySize, SMEM_BYTES);

    // 1) qkv = hidden @ Wqkv + bqkv : (2048,2560)x(2560,7680)
    sgemm128<<<dim3(7680 / 128, 2048 / 128), 256>>>(hidden, Wqkv, bqkv, qkv,
                                                    2048, 7680, 2560);

    // 2) fused quantum attention -> g_attn (2048,2560)
    attn_kernel<<<dim3(64, 64), 256, SMEM_BYTES>>>(qkv, gm, gp, ga, qp, isr, attn);

    // 3) out = attn @ Wproj + bproj : (2048,2560)x(2560,2560)
    sgemm128<<<dim3(2560 / 128, 2048 / 128), 256>>>(attn, Wproj, bproj, out,
                                                    2048, 2560, 2560);
}

// round 3
// speedup vs baseline: 1.5689x; 1.5689x over previous
#include <cuda_runtime.h>
#include <cuda_bf16.h>
#include <stdint.h>
#include <math.h>

// Problem constants: B=2, S=1024, E=2560, H=32, D=80, 3E=7680, BS=2048, K=2560

// ---------------- device scratch ----------------
__device__ float g_qkv[2048ull * 7680];
__device__ __nv_bfloat16 g_hid_hi[2048ull * 2560];
__device__ __nv_bfloat16 g_hid_lo[2048ull * 2560];
__device__ __nv_bfloat16 g_wqkvT_hi[7680ull * 2560];   // (N,K)
__device__ __nv_bfloat16 g_wqkvT_lo[7680ull * 2560];
__device__ __nv_bfloat16 g_wprojT_hi[2560ull * 2560];
__device__ __nv_bfloat16 g_wprojT_lo[2560ull * 2560];
__device__ __nv_bfloat16 g_attn_hi[2048ull * 2560];
__device__ __nv_bfloat16 g_attn_lo[2048ull * 2560];

__device__ __forceinline__ uint32_t smem_u32(const void* p) {
    uint32_t a;
    asm("{ .reg .u64 t; cvta.to.shared.u64 t, %1; cvt.u32.u64 %0, t; }"
        : "=r"(a) : "l"(p));
    return a;
}

#define SWZ(o) ((uint32_t)(o) ^ ((((uint32_t)(o)) >> 3) & 0x70u))

#define CP16(s, g) \
    asm volatile("cp.async.cg.shared.global [%0], [%1], 16;" :: "r"(s), "l"(g))

#define LDSM4(r, addr) \
    asm volatile("ldmatrix.sync.aligned.m8n8.x4.shared.b16 {%0,%1,%2,%3}, [%4];" \
                 : "=r"((r)[0]), "=r"((r)[1]), "=r"((r)[2]), "=r"((r)[3]) \
                 : "r"(addr))

#define MMA_BF16(acc, A, b0, b1) \
    asm volatile("mma.sync.aligned.m16n8k16.row.col.f32.bf16.bf16.f32 " \
                 "{%0,%1,%2,%3}, {%4,%5,%6,%7}, {%8,%9}, {%0,%1,%2,%3};" \
                 : "+f"((acc)[0]), "+f"((acc)[1]), "+f"((acc)[2]), "+f"((acc)[3]) \
                 : "r"((A)[0]), "r"((A)[1]), "r"((A)[2]), "r"((A)[3]), \
                   "r"(b0), "r"(b1))

// ---------------------------------------------------------------------------
// Conversion: fp32 -> bf16 hi/lo
// ---------------------------------------------------------------------------
__global__ void conv_hilo(const float* __restrict__ X,
                          __nv_bfloat16* __restrict__ Hh,
                          __nv_bfloat16* __restrict__ Ll, int n4) {
    int i = blockIdx.x * blockDim.x + threadIdx.x;
    if (i >= n4) return;
    float4 v = ((const float4*)X)[i];
    __nv_bfloat16 h0 = __float2bfloat16(v.x), h1 = __float2bfloat16(v.y);
    __nv_bfloat16 h2 = __float2bfloat16(v.z), h3 = __float2bfloat16(v.w);
    __nv_bfloat162 a, b;
    a.x = h0; a.y = h1; b.x = h2; b.y = h3;
    ((__nv_bfloat162*)Hh)[i * 2] = a;
    ((__nv_bfloat162*)Hh)[i * 2 + 1] = b;
    __nv_bfloat162 c, d;
    c.x = __float2bfloat16(v.x - __bfloat162float(h0));
    c.y = __float2bfloat16(v.y - __bfloat162float(h1));
    d.x = __float2bfloat16(v.z - __bfloat162float(h2));
    d.y = __float2bfloat16(v.w - __bfloat162float(h3));
    ((__nv_bfloat162*)Ll)[i * 2] = c;
    ((__nv_bfloat162*)Ll)[i * 2 + 1] = d;
}

// ---------------------------------------------------------------------------
// Transpose + convert: W (K,N) fp32 -> Th/Tl (N,K) bf16
// ---------------------------------------------------------------------------
__global__ void transpose_conv(const float* __restrict__ W,
                               __nv_bfloat16* __restrict__ Th,
                               __nv_bfloat16* __restrict__ Tl, int K, int N) {
    __shared__ float t[32][33];
    int n0 = blockIdx.x * 32, k0 = blockIdx.y * 32;
    int tx = threadIdx.x, ty = threadIdx.y;
#pragma unroll
    for (int j = 0; j < 4; j++)
        t[ty + j * 8][tx] = W[(size_t)(k0 + ty + j * 8) * N + n0 + tx];
    __syncthreads();
#pragma unroll
    for (int j = 0; j < 4; j++) {
        float v = t[tx][ty + j * 8];
        __nv_bfloat16 h = __float2bfloat16(v);
        size_t o = (size_t)(n0 + ty + j * 8) * K + k0 + tx;
        Th[o] = h;
        Tl[o] = __float2bfloat16(v - __bfloat162float(h));
    }
}

// ---------------------------------------------------------------------------
// mma.sync bf16x3 GEMM: C(2048,N) = A(2048,2560) @ B(N,2560)^T + bias
// CTA 128x128, 8 warps of 32x64, K chunks of 64, cp.async double buffer.
// smem stage (64KB): Ah 16K | Al 16K | Bh 16K | Bl 16K. Two stages = 128KB.
// ---------------------------------------------------------------------------
__global__ __launch_bounds__(256, 1) void gemm_bf16x3(
    const __nv_bfloat16* __restrict__ Ah, const __nv_bfloat16* __restrict__ Al,
    const __nv_bfloat16* __restrict__ Bh, const __nv_bfloat16* __restrict__ Bl,
    const float* __restrict__ bias, float* __restrict__ C, int N) {
    extern __shared__ __align__(1024) char dsm[];
    const uint32_t base = smem_u32(dsm);

    const int tid = threadIdx.x;
    const int wid = tid >> 5, lane = tid & 31;
    const int mw = wid & 3;       // warp m index (32 rows each)
    const int nw = wid >> 2;      // warp n index (64 cols each)
    const int mt = blockIdx.y, nt = blockIdx.x;
    const int K = 2560;

    const int trow = tid >> 3;    // 0..31
    const int tkg = tid & 7;      // 0..7 (16B chunk within 128B row)

    float acc[2][8][4];
#pragma unroll
    for (int a = 0; a < 2; a++)
#pragma unroll
        for (int b = 0; b < 8; b++)
#pragma unroll
            for (int c = 0; c < 4; c++) acc[a][b][c] = 0.0f;

    // per-chunk tile loader: 4 tiles x 4 rows/thread, 16B cp.async each
    auto load_chunk = [&](int c, int st) {
        const int k0 = c * 64;
        const uint32_t s0 = base + st * 65536;
#pragma unroll
        for (int j = 0; j < 4; j++) {
            const int row = j * 32 + trow;
            const uint32_t so = SWZ(row * 128 + tkg * 16);
            const __nv_bfloat16* ga = Ah + (size_t)(mt * 128 + row) * K + k0 + tkg * 8;
            const __nv_bfloat16* gal = Al + (size_t)(mt * 128 + row) * K + k0 + tkg * 8;
            const __nv_bfloat16* gb = Bh + (size_t)(nt * 128 + row) * K + k0 + tkg * 8;
            const __nv_bfloat16* gbl = Bl + (size_t)(nt * 128 + row) * K + k0 + tkg * 8;
            CP16(s0 + so, ga);
            CP16(s0 + 16384 + so, gal);
            CP16(s0 + 32768 + so, gb);
            CP16(s0 + 49152 + so, gbl);
        }
        asm volatile("cp.async.commit_group;");
    };

    const int lr = lane & 15;            // ldmatrix row within 16
    const int lc = (lane >> 4) * 16;     // 0 or 16 bytes (k half)

    load_chunk(0, 0);

    for (int c = 0; c < 40; c++) {
        const int st = c & 1;
        if (c < 39) {
            load_chunk(c + 1, st ^ 1);
            asm volatile("cp.async.wait_group 1;");
        } else {
            asm volatile("cp.async.wait_group 0;");
        }
        __syncthreads();

        const uint32_t sA = base + st * 65536;
#pragma unroll
        for (int ks = 0; ks < 4; ks++) {
            uint32_t ah[2][4], al[2][4];
#pragma unroll
            for (int mb = 0; mb < 2; mb++) {
                const uint32_t ro = (mw * 32 + mb * 16 + lr) * 128 + ks * 32 + lc;
                LDSM4(ah[mb], sA + SWZ(ro));
                LDSM4(al[mb], sA + 16384 + SWZ(ro));
            }
            uint32_t bh[4][4], bl[4][4];
#pragma unroll
            for (int nb = 0; nb < 4; nb++) {
                const uint32_t ro = (nw * 64 + nb * 16 + lr) * 128 + ks * 32 + lc;
                LDSM4(bh[nb], sA + 32768 + SWZ(ro));
                LDSM4(bl[nb], sA + 49152 + SWZ(ro));
            }
#pragma unroll
            for (int mb = 0; mb < 2; mb++) {
#pragma unroll
                for (int nb = 0; nb < 4; nb++) {
                    // x4 B reg order: {r0,r2} = first n8, {r1,r3} = second n8
                    MMA_BF16(acc[mb][nb * 2],     ah[mb], bh[nb][0], bh[nb][2]);
                    MMA_BF16(acc[mb][nb * 2],     ah[mb], bl[nb][0], bl[nb][2]);
                    MMA_BF16(acc[mb][nb * 2],     al[mb], bh[nb][0], bh[nb][2]);
                    MMA_BF16(acc[mb][nb * 2 + 1], ah[mb], bh[nb][1], bh[nb][3]);
                    MMA_BF16(acc[mb][nb * 2 + 1], ah[mb], bl[nb][1], bl[nb][3]);
                    MMA_BF16(acc[mb][nb * 2 + 1], al[mb], bh[nb][1], bh[nb][3]);
                }
            }
        }
        __syncthreads();
    }

    // epilogue
    const int row0 = mt * 128 + mw * 32 + (lane >> 2);
    const int col0 = nt * 128 + nw * 64 + 2 * (lane & 3);
#pragma unroll
    for (int mb = 0; mb < 2; mb++) {
#pragma unroll
        for (int n8 = 0; n8 < 8; n8++) {
            const int gc = col0 + n8 * 8;
            const float b0 = bias[gc], b1 = bias[gc + 1];
            const int r = row0 + mb * 16;
            float2 o0 = make_float2(acc[mb][n8][0] + b0, acc[mb][n8][1] + b1);
            float2 o1 = make_float2(acc[mb][n8][2] + b0, acc[mb][n8][3] + b1);
            *(float2*)&C[(size_t)r * N + gc] = o0;
            *(float2*)&C[(size_t)(r + 8) * N + gc] = o1;
        }
    }
}

// ---------------------------------------------------------------------------
// Fused quantum attention; emits bf16 hi/lo. ks rows padded to 84 floats for
// float4 smem loads (conflict-free).
// ---------------------------------------------------------------------------
__global__ __launch_bounds__(256) void attn_kernel(
    const float* __restrict__ qkv,
    const float* __restrict__ gm, const float* __restrict__ gp,
    const float* __restrict__ ga, const float* __restrict__ qp,
    const float* __restrict__ isr,
    __nv_bfloat16* __restrict__ out_hi, __nv_bfloat16* __restrict__ out_lo) {
    extern __shared__ float sm[];
    float* coeff = sm;            // 240
    float* row_l = sm + 240;      // 16
    float* qs    = sm + 256;      // 5120
    float* ks    = sm + 5376;     // 128*84 = 10752
    float* sc    = sm + 16128;    // 16*1040 = 16640  (total 32768 floats)

    const int tid  = threadIdx.x;
    const int warp = tid >> 5, lane = tid & 31;
    const int bh = blockIdx.y;
    const int b = bh >> 5, h = bh & 31;
    const int qt = blockIdx.x;

    if (tid < 240) {
        int g = tid / 80, d = tid - g * 80;
        float r0 = gm[g * 4 + 0] + gm[g * 4 + 1];
        float r1 = gm[g * 4 + 2] + gm[g * 4 + 3];
        float ph = gp[g * 80 + d];
        coeff[tid] = (cosf(ph) * r0 + sinf(ph) * r1) * ga[g * 80 + d];
    }
    __syncthreads();

    const float* qbase = qkv + (size_t)(b * 1024 + qt * 16) * 7680 + h * 80;
    for (int i = tid; i < 1280; i += 256) {
        int r = i / 80, d = i - r * 80;
        float v = qbase[(size_t)r * 7680 + d];
        qs[i]        = v;
        qs[1280 + i] = v * coeff[d];
        qs[2560 + i] = v * coeff[80 + d];
        qs[3840 + i] = v * coeff[160 + d];
    }

    const float scale = rsqrtf(80.0f);
    const float intf  = isr[0] * (1.0f / 3.0f);
    const float* kbase = qkv + (size_t)(b * 1024) * 7680 + 2560 + h * 80;
    const int r0 = warp * 2;

    // ---- Phase 1: scores ----
    for (int kt = 0; kt < 8; kt++) {
        __syncthreads();
        for (int i = tid; i < 2560; i += 256) {
            int key = i / 20, db = (i - key * 20) * 4;
            float4 f = *(const float4*)(kbase + (size_t)(kt * 128 + key) * 7680 + db);
            *(float4*)&ks[key * 84 + db] = f;
        }
        __syncthreads();

        float acc[2][4][4];
#pragma unroll
        for (int m = 0; m < 2; m++)
#pragma unroll
            for (int g = 0; g < 4; g++)
#pragma unroll
                for (int n = 0; n < 4; n++) acc[m][g][n] = 0.0f;

#pragma unroll 5
        for (int d = 0; d < 80; d += 4) {
            float4 kv0 = *(const float4*)&ks[lane * 84 + d];
            float4 kv1 = *(const float4*)&ks[(lane + 32) * 84 + d];
            float4 kv2 = *(const float4*)&ks[(lane + 64) * 84 + d];
            float4 kv3 = *(const float4*)&ks[(lane + 96) * 84 + d];
#pragma unroll
            for (int m = 0; m < 2; m++) {
#pragma unroll
                for (int g = 0; g < 4; g++) {
                    float4 qv = *(const float4*)&qs[g * 1280 + (r0 + m) * 80 + d];
                    acc[m][g][0] += qv.x * kv0.x + qv.y * kv0.y + qv.z * kv0.z + qv.w * kv0.w;
                    acc[m][g][1] += qv.x * kv1.x + qv.y * kv1.y + qv.z * kv1.z + qv.w * kv1.w;
                    acc[m][g][2] += qv.x * kv2.x + qv.y * kv2.y + qv.z * kv2.z + qv.w * kv2.w;
                    acc[m][g][3] += qv.x * kv3.x + qv.y * kv3.y + qv.z * kv3.z + qv.w * kv3.w;
                }
            }
        }

#pragma unroll
        for (int m = 0; m < 2; m++) {
            float* srow = sc + (r0 + m) * 1040 + kt * 128 + lane;
#pragma unroll
            for (int n = 0; n < 4; n++) {
                float s  = acc[m][0][n] * scale;
                float a0 = acc[m][1][n] * scale;
                float a1 = acc[m][2][n] * scale;
                float a2 = acc[m][3][n] * scale;
                srow[n * 32] = s + (a0 * a1 + a0 * a2 + a1 * a2) * intf;
            }
        }
    }
    __syncthreads();

    // ---- Phase 2: softmax ----
#pragma unroll
    for (int rr = 0; rr < 2; rr++) {
        int r = r0 + rr;
        float* row = sc + r * 1040;
        float mx = -1e30f;
#pragma unroll 8
        for (int j = 0; j < 32; j++) mx = fmaxf(mx, row[lane + j * 32]);
#pragma unroll
        for (int off = 16; off > 0; off >>= 1)
            mx = fmaxf(mx, __shfl_xor_sync(0xffffffffu, mx, off));
        float sum = 0.0f;
#pragma unroll 8
        for (int j = 0; j < 32; j++) {
            float p = __expf(row[lane + j * 32] - mx);
            row[lane + j * 32] = p;
            sum += p;
        }
#pragma unroll
        for (int off = 16; off > 0; off >>= 1)
            sum += __shfl_xor_sync(0xffffffffu, sum, off);
        if (lane == 0) row_l[r] = sum;
    }

    // ---- Phase 3: P @ V ----
    const int pr = tid >> 4;
    const int d0 = (tid & 15) * 5;
    float pacc[5] = {0, 0, 0, 0, 0};
    const float* vbase = qkv + (size_t)(b * 1024) * 7680 + 5120 + h * 80;

    for (int kt = 0; kt < 8; kt++) {
        __syncthreads();
        for (int i = tid; i < 2560; i += 256) {
            int key = i / 20, db = (i - key * 20) * 4;
            float4 f = *(const float4*)(vbase + (size_t)(kt * 128 + key) * 7680 + db);
            *(float4*)&ks[key * 84 + db] = f;
        }
        __syncthreads();
        const float* prow = sc + pr * 1040 + kt * 128;
#pragma unroll 4
        for (int k = 0; k < 128; k++) {
            float p = prow[k];
            const float* vv = ks + k * 84 + d0;
#pragma unroll
            for (int j = 0; j < 5; j++) pacc[j] += p * vv[j];
        }
    }

    float fac = cosf(qp[h]) / row_l[pr];
    size_t ob = (size_t)(b * 1024 + qt * 16 + pr) * 2560 + h * 80 + d0;
#pragma unroll
    for (int j = 0; j < 5; j++) {
        float v = pacc[j] * fac;
        __nv_bfloat16 hh = __float2bfloat16(v);
        out_hi[ob + j] = hh;
        out_lo[ob + j] = __float2bfloat16(v - __bfloat162float(hh));
    }
}

// ---------------------------------------------------------------------------
extern "C" void kernel_launch(void* const* d_in, const int* in_sizes, int n_in,
                              void* d_out, int out_size) {
    const float* hidden = (const float*)d_in[0];
    const float* Wqkv   = (const float*)d_in[1];
    const float* bqkv   = (const float*)d_in[2];
    const float* Wproj  = (const float*)d_in[3];
    const float* bproj  = (const float*)d_in[4];
    const float* gm     = (const float*)d_in[5];
    const float* gp     = (const float*)d_in[6];
    const float* ga     = (const float*)d_in[7];
    const float* qp     = (const float*)d_in[8];
    const float* isr    = (const float*)d_in[9];
    float* out = (float*)d_out;

    void *p_qkv, *p_hh, *p_hl, *p_wqh, *p_wql, *p_wph, *p_wpl, *p_ah, *p_al;
    cudaGetSymbolAddress(&p_qkv, g_qkv);
    cudaGetSymbolAddress(&p_hh, g_hid_hi);
    cudaGetSymbolAddress(&p_hl, g_hid_lo);
    cudaGetSymbolAddress(&p_wqh, g_wqkvT_hi);
    cudaGetSymbolAddress(&p_wql, g_wqkvT_lo);
    cudaGetSymbolAddress(&p_wph, g_wprojT_hi);
    cudaGetSymbolAddress(&p_wpl, g_wprojT_lo);
    cudaGetSymbolAddress(&p_ah, g_attn_hi);
    cudaGetSymbolAddress(&p_al, g_attn_lo);

    const int GEMM_SMEM = 131072;
    cudaFuncSetAttribute(gemm_bf16x3,
                         cudaFuncAttributeMaxDynamicSharedMemorySize, GEMM_SMEM);
    const int ATTN_SMEM = 32768 * 4;
    cudaFuncSetAttribute(attn_kernel,
                         cudaFuncAttributeMaxDynamicSharedMemorySize, ATTN_SMEM);

    // 1) conversions
    conv_hilo<<<5120, 256>>>(hidden, (__nv_bfloat16*)p_hh, (__nv_bfloat16*)p_hl,
                             2048 * 2560 / 4);
    transpose_conv<<<dim3(7680 / 32, 2560 / 32), dim3(32, 8)>>>(
        Wqkv, (__nv_bfloat16*)p_wqh, (__nv_bfloat16*)p_wql, 2560, 7680);
    transpose_conv<<<dim3(2560 / 32, 2560 / 32), dim3(32, 8)>>>(
        Wproj, (__nv_bfloat16*)p_wph, (__nv_bfloat16*)p_wpl, 2560, 2560);

    // 2) qkv = hidden @ Wqkv + bqkv
    gemm_bf16x3<<<dim3(60, 16), 256, GEMM_SMEM>>>(
        (const __nv_bfloat16*)p_hh, (const __nv_bfloat16*)p_hl,
        (const __nv_bfloat16*)p_wqh, (const __nv_bfloat16*)p_wql,
        bqkv, (float*)p_qkv, 7680);

    // 3) fused quantum attention -> bf16 hi/lo
    attn_kernel<<<dim3(64, 64), 256, ATTN_SMEM>>>(
        (const float*)p_qkv, gm, gp, ga, qp, isr,
        (__nv_bfloat16*)p_ah, (__nv_bfloat16*)p_al);

    // 4) out = attn @ Wproj + bproj
    gemm_bf16x3<<<dim3(20, 16), 256, GEMM_SMEM>>>(
        (const __nv_bfloat16*)p_ah, (const __nv_bfloat16*)p_al,
        (const __nv_bfloat16*)p_wph, (const __nv_bfloat16*)p_wpl,
        bproj, out, 2560);
}

// round 4
// speedup vs baseline: 2.8604x; 1.8232x over previous
#include <cuda_runtime.h>
#include <cuda_bf16.h>
#include <stdint.h>
#include <math.h>

// Problem constants: B=2, S=1024, E=2560, H=32, D=80, 3E=7680, BS=2048, K=2560

// ---------------- device scratch ----------------
__device__ float g_qkv[2048ull * 7680];
__device__ __nv_bfloat16 g_hid_hi[2048ull * 2560];
__device__ __nv_bfloat16 g_hid_lo[2048ull * 2560];
__device__ __nv_bfloat16 g_wqkvT_hi[7680ull * 2560];   // (N,K)
__device__ __nv_bfloat16 g_wqkvT_lo[7680ull * 2560];
__device__ __nv_bfloat16 g_wprojT_hi[2560ull * 2560];
__device__ __nv_bfloat16 g_wprojT_lo[2560ull * 2560];
__device__ __nv_bfloat16 g_attn_hi[2048ull * 2560];
__device__ __nv_bfloat16 g_attn_lo[2048ull * 2560];
__device__ __nv_bfloat16 g_Khi[64ull * 1024 * 88];     // [bh][key][88]
__device__ __nv_bfloat16 g_Klo[64ull * 1024 * 88];
__device__ __nv_bfloat16 g_Vthi[64ull * 80 * 1024];    // [bh][dim][1024]
__device__ __nv_bfloat16 g_Vtlo[64ull * 80 * 1024];

__device__ __forceinline__ uint32_t smem_u32(const void* p) {
    uint32_t a;
    asm("{ .reg .u64 t; cvta.to.shared.u64 t, %1; cvt.u32.u64 %0, t; }"
        : "=r"(a) : "l"(p));
    return a;
}

#define SWZ(o) ((uint32_t)(o) ^ ((((uint32_t)(o)) >> 3) & 0x70u))

#define CP16(s, g) \
    asm volatile("cp.async.cg.shared.global [%0], [%1], 16;" :: "r"(s), "l"(g))

#define LDSM4(r, addr) \
    asm volatile("ldmatrix.sync.aligned.m8n8.x4.shared.b16 {%0,%1,%2,%3}, [%4];" \
                 : "=r"((r)[0]), "=r"((r)[1]), "=r"((r)[2]), "=r"((r)[3]) \
                 : "r"(addr))

#define MMA_BF16(acc, A, b0, b1) \
    asm volatile("mma.sync.aligned.m16n8k16.row.col.f32.bf16.bf16.f32 " \
                 "{%0,%1,%2,%3}, {%4,%5,%6,%7}, {%8,%9}, {%0,%1,%2,%3};" \
                 : "+f"((acc)[0]), "+f"((acc)[1]), "+f"((acc)[2]), "+f"((acc)[3]) \
                 : "r"((A)[0]), "r"((A)[1]), "r"((A)[2]), "r"((A)[3]), \
                   "r"(b0), "r"(b1))

// ---------------------------------------------------------------------------
// Conversion: fp32 -> bf16 hi/lo
// ---------------------------------------------------------------------------
__global__ void conv_hilo(const float* __restrict__ X,
                          __nv_bfloat16* __restrict__ Hh,
                          __nv_bfloat16* __restrict__ Ll, int n4) {
    int i = blockIdx.x * blockDim.x + threadIdx.x;
    if (i >= n4) return;
    float4 v = ((const float4*)X)[i];
    __nv_bfloat16 h0 = __float2bfloat16(v.x), h1 = __float2bfloat16(v.y);
    __nv_bfloat16 h2 = __float2bfloat16(v.z), h3 = __float2bfloat16(v.w);
    __nv_bfloat162 a, b;
    a.x = h0; a.y = h1; b.x = h2; b.y = h3;
    ((__nv_bfloat162*)Hh)[i * 2] = a;
    ((__nv_bfloat162*)Hh)[i * 2 + 1] = b;
    __nv_bfloat162 c, d;
    c.x = __float2bfloat16(v.x - __bfloat162float(h0));
    c.y = __float2bfloat16(v.y - __bfloat162float(h1));
    d.x = __float2bfloat16(v.z - __bfloat162float(h2));
    d.y = __float2bfloat16(v.w - __bfloat162float(h3));
    ((__nv_bfloat162*)Ll)[i * 2] = c;
    ((__nv_bfloat162*)Ll)[i * 2 + 1] = d;
}

// ---------------------------------------------------------------------------
// Transpose + convert: W (K,N) fp32 -> Th/Tl (N,K) bf16
// ---------------------------------------------------------------------------
__global__ void transpose_conv(const float* __restrict__ W,
                               __nv_bfloat16* __restrict__ Th,
                               __nv_bfloat16* __restrict__ Tl, int K, int N) {
    __shared__ float t[32][33];
    int n0 = blockIdx.x * 32, k0 = blockIdx.y * 32;
    int tx = threadIdx.x, ty = threadIdx.y;
#pragma unroll
    for (int j = 0; j < 4; j++)
        t[ty + j * 8][tx] = W[(size_t)(k0 + ty + j * 8) * N + n0 + tx];
    __syncthreads();
#pragma unroll
    for (int j = 0; j < 4; j++) {
        float v = t[tx][ty + j * 8];
        __nv_bfloat16 h = __float2bfloat16(v);
        size_t o = (size_t)(n0 + ty + j * 8) * K + k0 + tx;
        Th[o] = h;
        Tl[o] = __float2bfloat16(v - __bfloat162float(h));
    }
}

// ---------------------------------------------------------------------------
// prep_k: k part of qkv -> bf16 hi/lo [bh][key][88] (cols 80..87 unused pad)
// ---------------------------------------------------------------------------
__global__ void prep_k(const float* __restrict__ qkv,
                       __nv_bfloat16* __restrict__ Kh,
                       __nv_bfloat16* __restrict__ Kl) {
    int idx = blockIdx.x * 256 + threadIdx.x;
    if (idx >= 64 * 1024 * 80) return;
    int d = idx % 80;
    int key = (idx / 80) & 1023;
    int bh = idx / 81920;
    int b = bh >> 5, h = bh & 31;
    float v = qkv[(size_t)(b * 1024 + key) * 7680 + 2560 + h * 80 + d];
    __nv_bfloat16 hh = __float2bfloat16(v);
    size_t o = (size_t)bh * 90112 + key * 88 + d;
    Kh[o] = hh;
    Kl[o] = __float2bfloat16(v - __bfloat162float(hh));
}

// ---------------------------------------------------------------------------
// prep_vt: v part -> transposed bf16 hi/lo [bh][dim][1024]
// grid (64 keytiles, 5 dimtiles, 64 bh), block (16,16)
// ---------------------------------------------------------------------------
__global__ void prep_vt(const float* __restrict__ qkv,
                        __nv_bfloat16* __restrict__ Vh,
                        __nv_bfloat16* __restrict__ Vl) {
    __shared__ float t[16][17];
    int kt = blockIdx.x, dt = blockIdx.y, bh = blockIdx.z;
    int b = bh >> 5, h = bh & 31;
    int tx = threadIdx.x, ty = threadIdx.y;
    t[ty][tx] = qkv[(size_t)(b * 1024 + kt * 16 + ty) * 7680 + 5120 + h * 80 +
                    dt * 16 + tx];
    __syncthreads();
    float v = t[tx][ty];
    __nv_bfloat16 hh = __float2bfloat16(v);
    size_t o = ((size_t)bh * 80 + dt * 16 + ty) * 1024 + kt * 16 + tx;
    Vh[o] = hh;
    Vl[o] = __float2bfloat16(v - __bfloat162float(hh));
}

// ---------------------------------------------------------------------------
// mma.sync bf16x3 GEMM (unchanged, proven): C(2048,N) = A @ B^T + bias
// ---------------------------------------------------------------------------
__global__ __launch_bounds__(256, 1) void gemm_bf16x3(
    const __nv_bfloat16* __restrict__ Ah, const __nv_bfloat16* __restrict__ Al,
    const __nv_bfloat16* __restrict__ Bh, const __nv_bfloat16* __restrict__ Bl,
    const float* __restrict__ bias, float* __restrict__ C, int N) {
    extern __shared__ __align__(1024) char dsm[];
    const uint32_t base = smem_u32(dsm);

    const int tid = threadIdx.x;
    const int wid = tid >> 5, lane = tid & 31;
    const int mw = wid & 3;
    const int nw = wid >> 2;
    const int mt = blockIdx.y, nt = blockIdx.x;
    const int K = 2560;

    const int trow = tid >> 3;
    const int tkg = tid & 7;

    float acc[2][8][4];
#pragma unroll
    for (int a = 0; a < 2; a++)
#pragma unroll
        for (int b = 0; b < 8; b++)
#pragma unroll
            for (int c = 0; c < 4; c++) acc[a][b][c] = 0.0f;

    auto load_chunk = [&](int c, int st) {
        const int k0 = c * 64;
        const uint32_t s0 = base + st * 65536;
#pragma unroll
        for (int j = 0; j < 4; j++) {
            const int row = j * 32 + trow;
            const uint32_t so = SWZ(row * 128 + tkg * 16);
            const __nv_bfloat16* ga = Ah + (size_t)(mt * 128 + row) * K + k0 + tkg * 8;
            const __nv_bfloat16* gal = Al + (size_t)(mt * 128 + row) * K + k0 + tkg * 8;
            const __nv_bfloat16* gb = Bh + (size_t)(nt * 128 + row) * K + k0 + tkg * 8;
            const __nv_bfloat16* gbl = Bl + (size_t)(nt * 128 + row) * K + k0 + tkg * 8;
            CP16(s0 + so, ga);
            CP16(s0 + 16384 + so, gal);
            CP16(s0 + 32768 + so, gb);
            CP16(s0 + 49152 + so, gbl);
        }
        asm volatile("cp.async.commit_group;");
    };

    const int lr = lane & 15;
    const int lc = (lane >> 4) * 16;

    load_chunk(0, 0);

    for (int c = 0; c < 40; c++) {
        const int st = c & 1;
        if (c < 39) {
            load_chunk(c + 1, st ^ 1);
            asm volatile("cp.async.wait_group 1;");
        } else {
            asm volatile("cp.async.wait_group 0;");
        }
        __syncthreads();

        const uint32_t sA = base + st * 65536;
#pragma unroll
        for (int ks = 0; ks < 4; ks++) {
            uint32_t ah[2][4], al[2][4];
#pragma unroll
            for (int mb = 0; mb < 2; mb++) {
                const uint32_t ro = (mw * 32 + mb * 16 + lr) * 128 + ks * 32 + lc;
                LDSM4(ah[mb], sA + SWZ(ro));
                LDSM4(al[mb], sA + 16384 + SWZ(ro));
            }
            uint32_t bh[4][4], bl[4][4];
#pragma unroll
            for (int nb = 0; nb < 4; nb++) {
                const uint32_t ro = (nw * 64 + nb * 16 + lr) * 128 + ks * 32 + lc;
                LDSM4(bh[nb], sA + 32768 + SWZ(ro));
                LDSM4(bl[nb], sA + 49152 + SWZ(ro));
            }
#pragma unroll
            for (int mb = 0; mb < 2; mb++) {
#pragma unroll
                for (int nb = 0; nb < 4; nb++) {
                    MMA_BF16(acc[mb][nb * 2],     ah[mb], bh[nb][0], bh[nb][2]);
                    MMA_BF16(acc[mb][nb * 2],     ah[mb], bl[nb][0], bl[nb][2]);
                    MMA_BF16(acc[mb][nb * 2],     al[mb], bh[nb][0], bh[nb][2]);
                    MMA_BF16(acc[mb][nb * 2 + 1], ah[mb], bh[nb][1], bh[nb][3]);
                    MMA_BF16(acc[mb][nb * 2 + 1], ah[mb], bl[nb][1], bl[nb][3]);
                    MMA_BF16(acc[mb][nb * 2 + 1], al[mb], bh[nb][1], bh[nb][3]);
                }
            }
        }
        __syncthreads();
    }

    const int row0 = mt * 128 + mw * 32 + (lane >> 2);
    const int col0 = nt * 128 + nw * 64 + 2 * (lane & 3);
#pragma unroll
    for (int mb = 0; mb < 2; mb++) {
#pragma unroll
        for (int n8 = 0; n8 < 8; n8++) {
            const int gc = col0 + n8 * 8;
            const float b0 = bias[gc], b1 = bias[gc + 1];
            const int r = row0 + mb * 16;
            float2 o0 = make_float2(acc[mb][n8][0] + b0, acc[mb][n8][1] + b1);
            float2 o1 = make_float2(acc[mb][n8][2] + b0, acc[mb][n8][3] + b1);
            *(float2*)&C[(size_t)r * N + gc] = o0;
            *(float2*)&C[(size_t)(r + 8) * N + gc] = o1;
        }
    }
}

// ---------------------------------------------------------------------------
// attn_mma: tensor-core quantum attention.
// CTA = (bh, 16 q rows). Qext = 64 rows (4 variants x 16q), pitch 176B.
// Phase1: scores via bf16x3 mma -> variant scratch -> combined sc (fp32).
// Phase2: softmax -> P bf16 hi/lo (pitch 2064B) + rowsums.
// Phase3: P@V via bf16x3 mma (V transposed tiles, pitch 272B) -> reduce -> out.
// smem overlays (bytes):
//  ph1: QH 0..11264 | QL ..22528 | KH ..45056 | KL ..67584 | SCR ..101376 | SC ..167424
//  ph23: PH 0..33024 | PL ..66048 | V 67584..154624 (2 st x (hi 21760 + lo 21760)) | RED 154624..197632
// ---------------------------------------------------------------------------
#define A_OFF_QH 0u
#define A_OFF_QL 11264u
#define A_OFF_KH 22528u
#define A_OFF_KL 45056u
#define A_OFF_SCR 67584u
#define A_OFF_SC 101376u
#define A_OFF_PH 0u
#define A_OFF_PL 33024u
#define A_OFF_V 67584u
#define A_OFF_RED 154624u
#define A_SMEM 197632

__global__ __launch_bounds__(256, 1) void attn_mma(
    const float* __restrict__ qkv,
    const __nv_bfloat16* __restrict__ Kh, const __nv_bfloat16* __restrict__ Kl,
    const __nv_bfloat16* __restrict__ Vh, const __nv_bfloat16* __restrict__ Vl,
    const float* __restrict__ gm, const float* __restrict__ gp,
    const float* __restrict__ ga, const float* __restrict__ qp,
    const float* __restrict__ isr,
    __nv_bfloat16* __restrict__ out_hi, __nv_bfloat16* __restrict__ out_lo) {
    extern __shared__ __align__(128) char smc[];
    __shared__ float coeff[240];
    __shared__ float row_l[16];
    char* sm = smc;
    const uint32_t base = smem_u32(smc);

    const int tid = threadIdx.x;
    const int wid = tid >> 5, lane = tid & 31;
    const int lr = lane & 15, lc = (lane >> 4) << 4;
    const int rr = lane >> 2, cc = (lane & 3) * 2;
    const int bh = blockIdx.y, b = bh >> 5, h = bh & 31;
    const int q0 = blockIdx.x * 16;

    if (tid < 240) {
        int g = tid / 80, d = tid - g * 80;
        float r0 = gm[g * 4 + 0] + gm[g * 4 + 1];
        float r1 = gm[g * 4 + 2] + gm[g * 4 + 3];
        float ph = gp[g * 80 + d];
        coeff[tid] = (cosf(ph) * r0 + sinf(ph) * r1) * ga[g * 80 + d];
    }
    __syncthreads();

    // build Qext (4 variants x 16 rows x 80 dims, scale folded in)
    const float scale = rsqrtf(80.0f);
    for (int idx = tid; idx < 1280; idx += 256) {
        int r = idx / 80, d = idx - r * 80;
        float v = qkv[(size_t)(b * 1024 + q0 + r) * 7680 + h * 80 + d] * scale;
        float vv[4] = {v, v * coeff[d], v * coeff[80 + d], v * coeff[160 + d]};
#pragma unroll
        for (int g = 0; g < 4; g++) {
            uint32_t o = (g * 16 + r) * 176 + d * 2;
            __nv_bfloat16 hh = __float2bfloat16(vv[g]);
            *(__nv_bfloat16*)(sm + A_OFF_QH + o) = hh;
            *(__nv_bfloat16*)(sm + A_OFF_QL + o) =
                __float2bfloat16(vv[g] - __bfloat162float(hh));
        }
    }

    const __nv_bfloat16* KhB = Kh + (size_t)bh * 90112;
    const __nv_bfloat16* KlB = Kl + (size_t)bh * 90112;
    auto load_k = [&](int kt) {
#pragma unroll
        for (int j = 0; j < 11; j++) {
            int idx = tid + j * 256;
            int m = idx >= 1408;
            int rem = m ? idx - 1408 : idx;
            int row = rem / 11, ch = rem - row * 11;
            const __nv_bfloat16* g =
                (m ? KlB : KhB) + (size_t)(kt * 128 + row) * 88 + ch * 8;
            CP16(base + (m ? A_OFF_KL : A_OFF_KH) + row * 176 + ch * 16, g);
        }
        asm volatile("cp.async.commit_group;");
    };

    load_k(0);
    const float intf = isr[0] * (1.0f / 3.0f);

    const int vr = wid & 3, nh = wid >> 2;
    float* scrv = (float*)(sm + A_OFF_SCR) + vr * 2112;   // 16 x 132
    float* sc = (float*)(sm + A_OFF_SC);                  // 16 x 1032

    // ---- Phase 1: scores ----
    for (int kt = 0; kt < 8; kt++) {
        asm volatile("cp.async.wait_group 0;");
        __syncthreads();

        float acc[8][4];
#pragma unroll
        for (int i = 0; i < 8; i++)
#pragma unroll
            for (int j = 0; j < 4; j++) acc[i][j] = 0.0f;

#pragma unroll
        for (int ks = 0; ks < 5; ks++) {
            uint32_t aH[4], aL[4];
            uint32_t ro = (vr * 16 + lr) * 176 + ks * 32 + lc;
            LDSM4(aH, base + A_OFF_QH + ro);
            LDSM4(aL, base + A_OFF_QL + ro);
#pragma unroll
            for (int nb = 0; nb < 4; nb++) {
                uint32_t bH[4], bL[4];
                uint32_t rb = (nh * 64 + nb * 16 + lr) * 176 + ks * 32 + lc;
                LDSM4(bH, base + A_OFF_KH + rb);
                LDSM4(bL, base + A_OFF_KL + rb);
                MMA_BF16(acc[nb * 2],     aH, bH[0], bH[2]);
                MMA_BF16(acc[nb * 2],     aH, bL[0], bL[2]);
                MMA_BF16(acc[nb * 2],     aL, bH[0], bH[2]);
                MMA_BF16(acc[nb * 2 + 1], aH, bH[1], bH[3]);
                MMA_BF16(acc[nb * 2 + 1], aH, bL[1], bL[3]);
                MMA_BF16(acc[nb * 2 + 1], aL, bH[1], bH[3]);
            }
        }
#pragma unroll
        for (int n8 = 0; n8 < 8; n8++) {
            int c = nh * 64 + n8 * 8 + cc;
            scrv[rr * 132 + c]           = acc[n8][0];
            scrv[rr * 132 + c + 1]       = acc[n8][1];
            scrv[(rr + 8) * 132 + c]     = acc[n8][2];
            scrv[(rr + 8) * 132 + c + 1] = acc[n8][3];
        }
        __syncthreads();
        if (kt < 7) load_k(kt + 1);

        const float* s0 = (const float*)(sm + A_OFF_SCR);
#pragma unroll
        for (int j = 0; j < 8; j++) {
            int idx = tid + j * 256;
            int r = idx >> 7, c = idx & 127;
            float s  = s0[r * 132 + c];
            float a0 = s0[2112 + r * 132 + c];
            float a1 = s0[4224 + r * 132 + c];
            float a2 = s0[6336 + r * 132 + c];
            sc[r * 1032 + kt * 128 + c] = s + (a0 * a1 + a0 * a2 + a1 * a2) * intf;
        }
        __syncthreads();
    }

    // ---- Phase 2: softmax -> P (bf16 hi/lo) ----
#pragma unroll
    for (int t2 = 0; t2 < 2; t2++) {
        int r = wid * 2 + t2;
        const float* row = sc + r * 1032;
        float mx = -1e30f;
#pragma unroll 8
        for (int j = 0; j < 32; j++) mx = fmaxf(mx, row[lane + j * 32]);
#pragma unroll
        for (int off = 16; off > 0; off >>= 1)
            mx = fmaxf(mx, __shfl_xor_sync(0xffffffffu, mx, off));
        float sum = 0.0f;
#pragma unroll 8
        for (int j = 0; j < 32; j++) {
            int c = lane + j * 32;
            float p = __expf(row[c] - mx);
            sum += p;
            __nv_bfloat16 hh = __float2bfloat16(p);
            *(__nv_bfloat16*)(sm + A_OFF_PH + r * 2064 + c * 2) = hh;
            *(__nv_bfloat16*)(sm + A_OFF_PL + r * 2064 + c * 2) =
                __float2bfloat16(p - __bfloat162float(hh));
        }
#pragma unroll
        for (int off = 16; off > 0; off >>= 1)
            sum += __shfl_xor_sync(0xffffffffu, sum, off);
        if (lane == 0) row_l[r] = sum;
    }
    __syncthreads();

    // ---- Phase 3: P @ V ----
    const __nv_bfloat16* VhB = Vh + (size_t)bh * 81920;
    const __nv_bfloat16* VlB = Vl + (size_t)bh * 81920;
    auto load_v = [&](int kt, int st) {
#pragma unroll
        for (int j = 0; j < 10; j++) {
            int idx = tid + j * 256;
            int m = idx >= 1280;
            int rem = m ? idx - 1280 : idx;
            int dim = rem >> 4, ch = rem & 15;
            const __nv_bfloat16* g =
                (m ? VlB : VhB) + (size_t)dim * 1024 + kt * 128 + ch * 8;
            CP16(base + A_OFF_V + st * 43520 + m * 21760 + dim * 272 + ch * 16, g);
        }
        asm volatile("cp.async.commit_group;");
    };

    load_v(0, 0);
    float acc[10][4];
#pragma unroll
    for (int i = 0; i < 10; i++)
#pragma unroll
        for (int j = 0; j < 4; j++) acc[i][j] = 0.0f;

    for (int kt = 0; kt < 8; kt++) {
        const int st = kt & 1;
        if (kt < 7) {
            load_v(kt + 1, st ^ 1);
            asm volatile("cp.async.wait_group 1;");
        } else {
            asm volatile("cp.async.wait_group 0;");
        }
        __syncthreads();

        uint32_t aH[4], aL[4];
        uint32_t ro = lr * 2064 + kt * 256 + wid * 32 + lc;
        LDSM4(aH, base + A_OFF_PH + ro);
        LDSM4(aL, base + A_OFF_PL + ro);
#pragma unroll
        for (int nd = 0; nd < 5; nd++) {
            uint32_t bH[4], bL[4];
            uint32_t rb = st * 43520 + (nd * 16 + lr) * 272 + wid * 32 + lc;
            LDSM4(bH, base + A_OFF_V + rb);
            LDSM4(bL, base + A_OFF_V + 21760 + rb);
            MMA_BF16(acc[nd * 2],     aH, bH[0], bH[2]);
            MMA_BF16(acc[nd * 2],     aH, bL[0], bL[2]);
            MMA_BF16(acc[nd * 2],     aL, bH[0], bH[2]);
            MMA_BF16(acc[nd * 2 + 1], aH, bH[1], bH[3]);
            MMA_BF16(acc[nd * 2 + 1], aH, bL[1], bL[3]);
            MMA_BF16(acc[nd * 2 + 1], aL, bH[1], bH[3]);
        }
        __syncthreads();
    }

    // cross-warp reduce over key slices
    float* red = (float*)(sm + A_OFF_RED);
    float* redw = red + wid * 1344;   // 16 x 84
#pragma unroll
    for (int j = 0; j < 10; j++) {
        int d = (j >> 1) * 16 + (j & 1) * 8 + cc;
        redw[rr * 84 + d]           = acc[j][0];
        redw[rr * 84 + d + 1]       = acc[j][1];
        redw[(rr + 8) * 84 + d]     = acc[j][2];
        redw[(rr + 8) * 84 + d + 1] = acc[j][3];
    }
    __syncthreads();

    const float cph = cosf(qp[h]);
    for (int idx = tid; idx < 1280; idx += 256) {
        int r = idx / 80, d = idx - r * 80;
        float s = 0.0f;
#pragma unroll
        for (int w = 0; w < 8; w++) s += red[w * 1344 + r * 84 + d];
        float o = s * cph / row_l[r];
        size_t go = (size_t)(b * 1024 + q0 + r) * 2560 + h * 80 + d;
        __nv_bfloat16 hh = __float2bfloat16(o);
        out_hi[go] = hh;
        out_lo[go] = __float2bfloat16(o - __bfloat162float(hh));
    }
}

// ---------------------------------------------------------------------------
extern "C" void kernel_launch(void* const* d_in, const int* in_sizes, int n_in,
                              void* d_out, int out_size) {
    const float* hidden = (const float*)d_in[0];
    const float* Wqkv   = (const float*)d_in[1];
    const float* bqkv   = (const float*)d_in[2];
    const float* Wproj  = (const float*)d_in[3];
    const float* bproj  = (const float*)d_in[4];
    const float* gm     = (const float*)d_in[5];
    const float* gp     = (const float*)d_in[6];
    const float* ga     = (const float*)d_in[7];
    const float* qp     = (const float*)d_in[8];
    const float* isr    = (const float*)d_in[9];
    float* out = (float*)d_out;

    void *p_qkv, *p_hh, *p_hl, *p_wqh, *p_wql, *p_wph, *p_wpl, *p_ah, *p_al;
    void *p_kh, *p_kl, *p_vh, *p_vl;
    cudaGetSymbolAddress(&p_qkv, g_qkv);
    cudaGetSymbolAddress(&p_hh, g_hid_hi);
    cudaGetSymbolAddress(&p_hl, g_hid_lo);
    cudaGetSymbolAddress(&p_wqh, g_wqkvT_hi);
    cudaGetSymbolAddress(&p_wql, g_wqkvT_lo);
    cudaGetSymbolAddress(&p_wph, g_wprojT_hi);
    cudaGetSymbolAddress(&p_wpl, g_wprojT_lo);
    cudaGetSymbolAddress(&p_ah, g_attn_hi);
    cudaGetSymbolAddress(&p_al, g_attn_lo);
    cudaGetSymbolAddress(&p_kh, g_Khi);
    cudaGetSymbolAddress(&p_kl, g_Klo);
    cudaGetSymbolAddress(&p_vh, g_Vthi);
    cudaGetSymbolAddress(&p_vl, g_Vtlo);

    const int GEMM_SMEM = 131072;
    cudaFuncSetAttribute(gemm_bf16x3,
                         cudaFuncAttributeMaxDynamicSharedMemorySize, GEMM_SMEM);
    cudaFuncSetAttribute(attn_mma,
                         cudaFuncAttributeMaxDynamicSharedMemorySize, A_SMEM);

    // 1) input conversions
    conv_hilo<<<5120, 256>>>(hidden, (__nv_bfloat16*)p_hh, (__nv_bfloat16*)p_hl,
                             2048 * 2560 / 4);
    transpose_conv<<<dim3(7680 / 32, 2560 / 32), dim3(32, 8)>>>(
        Wqkv, (__nv_bfloat16*)p_wqh, (__nv_bfloat16*)p_wql, 2560, 7680);
    transpose_conv<<<dim3(2560 / 32, 2560 / 32), dim3(32, 8)>>>(
        Wproj, (__nv_bfloat16*)p_wph, (__nv_bfloat16*)p_wpl, 2560, 2560);

    // 2) qkv = hidden @ Wqkv + bqkv
    gemm_bf16x3<<<dim3(60, 16), 256, GEMM_SMEM>>>(
        (const __nv_bfloat16*)p_hh, (const __nv_bfloat16*)p_hl,
        (const __nv_bfloat16*)p_wqh, (const __nv_bfloat16*)p_wql,
        bqkv, (float*)p_qkv, 7680);

    // 3) K/V conversion for tensor-core attention
    prep_k<<<20480, 256>>>((const float*)p_qkv, (__nv_bfloat16*)p_kh,
                           (__nv_bfloat16*)p_kl);
    prep_vt<<<dim3(64, 5, 64), dim3(16, 16)>>>(
        (const float*)p_qkv, (__nv_bfloat16*)p_vh, (__nv_bfloat16*)p_vl);

    // 4) tensor-core quantum attention -> bf16 hi/lo
    attn_mma<<<dim3(64, 64), 256, A_SMEM>>>(
        (const float*)p_qkv,
        (const __nv_bfloat16*)p_kh, (const __nv_bfloat16*)p_kl,
        (const __nv_bfloat16*)p_vh, (const __nv_bfloat16*)p_vl,
        gm, gp, ga, qp, isr,
        (__nv_bfloat16*)p_ah, (__nv_bfloat16*)p_al);

    // 5) out = attn @ Wproj + bproj
    gemm_bf16x3<<<dim3(20, 16), 256, GEMM_SMEM>>>(
        (const __nv_bfloat16*)p_ah, (const __nv_bfloat16*)p_al,
        (const __nv_bfloat16*)p_wph, (const __nv_bfloat16*)p_wpl,
        bproj, out, 2560);
}

// round 5
// speedup vs baseline: 2.8818x; 1.0075x over previous
#include <cuda_runtime.h>
#include <cuda_bf16.h>
#include <stdint.h>
#include <math.h>

// Problem constants: B=2, S=1024, E=2560, H=32, D=80, 3E=7680, BS=2048, K=2560

// ---------------- device scratch ----------------
__device__ float g_qkv[2048ull * 7680];
__device__ __nv_bfloat16 g_hid_hi[2048ull * 2560];
__device__ __nv_bfloat16 g_hid_lo[2048ull * 2560];
__device__ __nv_bfloat16 g_wqkvT_hi[7680ull * 2560];   // (N,K)
__device__ __nv_bfloat16 g_wqkvT_lo[7680ull * 2560];
__device__ __nv_bfloat16 g_wprojT_hi[2560ull * 2560];
__device__ __nv_bfloat16 g_wprojT_lo[2560ull * 2560];
__device__ __nv_bfloat16 g_attn_hi[2048ull * 2560];
__device__ __nv_bfloat16 g_attn_lo[2048ull * 2560];
__device__ __nv_bfloat16 g_Khi[64ull * 1024 * 88];     // [bh][key][88]
__device__ __nv_bfloat16 g_Klo[64ull * 1024 * 88];
__device__ __nv_bfloat16 g_Vthi[64ull * 80 * 1024];    // [bh][dim][1024]
__device__ __nv_bfloat16 g_Vtlo[64ull * 80 * 1024];

__device__ __forceinline__ uint32_t smem_u32(const void* p) {
    uint32_t a;
    asm("{ .reg .u64 t; cvta.to.shared.u64 t, %1; cvt.u32.u64 %0, t; }"
        : "=r"(a) : "l"(p));
    return a;
}

#define SWZ(o) ((uint32_t)(o) ^ ((((uint32_t)(o)) >> 3) & 0x70u))

#define CP16(s, g) \
    asm volatile("cp.async.cg.shared.global [%0], [%1], 16;" :: "r"(s), "l"(g))

#define LDSM4(r, addr) \
    asm volatile("ldmatrix.sync.aligned.m8n8.x4.shared.b16 {%0,%1,%2,%3}, [%4];" \
                 : "=r"((r)[0]), "=r"((r)[1]), "=r"((r)[2]), "=r"((r)[3]) \
                 : "r"(addr))

#define MMA_BF16(acc, A, b0, b1) \
    asm volatile("mma.sync.aligned.m16n8k16.row.col.f32.bf16.bf16.f32 " \
                 "{%0,%1,%2,%3}, {%4,%5,%6,%7}, {%8,%9}, {%0,%1,%2,%3};" \
                 : "+f"((acc)[0]), "+f"((acc)[1]), "+f"((acc)[2]), "+f"((acc)[3]) \
                 : "r"((A)[0]), "r"((A)[1]), "r"((A)[2]), "r"((A)[3]), \
                   "r"(b0), "r"(b1))

// ---------------------------------------------------------------------------
// Conversion: fp32 -> bf16 hi/lo
// ---------------------------------------------------------------------------
__global__ void conv_hilo(const float* __restrict__ X,
                          __nv_bfloat16* __restrict__ Hh,
                          __nv_bfloat16* __restrict__ Ll, int n4) {
    int i = blockIdx.x * blockDim.x + threadIdx.x;
    if (i >= n4) return;
    float4 v = ((const float4*)X)[i];
    __nv_bfloat16 h0 = __float2bfloat16(v.x), h1 = __float2bfloat16(v.y);
    __nv_bfloat16 h2 = __float2bfloat16(v.z), h3 = __float2bfloat16(v.w);
    __nv_bfloat162 a, b;
    a.x = h0; a.y = h1; b.x = h2; b.y = h3;
    ((__nv_bfloat162*)Hh)[i * 2] = a;
    ((__nv_bfloat162*)Hh)[i * 2 + 1] = b;
    __nv_bfloat162 c, d;
    c.x = __float2bfloat16(v.x - __bfloat162float(h0));
    c.y = __float2bfloat16(v.y - __bfloat162float(h1));
    d.x = __float2bfloat16(v.z - __bfloat162float(h2));
    d.y = __float2bfloat16(v.w - __bfloat162float(h3));
    ((__nv_bfloat162*)Ll)[i * 2] = c;
    ((__nv_bfloat162*)Ll)[i * 2 + 1] = d;
}

// ---------------------------------------------------------------------------
// Transpose + convert: W (K,N) fp32 -> Th/Tl (N,K) bf16
// ---------------------------------------------------------------------------
__global__ void transpose_conv(const float* __restrict__ W,
                               __nv_bfloat16* __restrict__ Th,
                               __nv_bfloat16* __restrict__ Tl, int K, int N) {
    __shared__ float t[32][33];
    int n0 = blockIdx.x * 32, k0 = blockIdx.y * 32;
    int tx = threadIdx.x, ty = threadIdx.y;
#pragma unroll
    for (int j = 0; j < 4; j++)
        t[ty + j * 8][tx] = W[(size_t)(k0 + ty + j * 8) * N + n0 + tx];
    __syncthreads();
#pragma unroll
    for (int j = 0; j < 4; j++) {
        float v = t[tx][ty + j * 8];
        __nv_bfloat16 h = __float2bfloat16(v);
        size_t o = (size_t)(n0 + ty + j * 8) * K + k0 + tx;
        Th[o] = h;
        Tl[o] = __float2bfloat16(v - __bfloat162float(h));
    }
}

// ---------------------------------------------------------------------------
// prep_k: k part of qkv -> bf16 hi/lo [bh][key][88]
// ---------------------------------------------------------------------------
__global__ void prep_k(const float* __restrict__ qkv,
                       __nv_bfloat16* __restrict__ Kh,
                       __nv_bfloat16* __restrict__ Kl) {
    int idx = blockIdx.x * 256 + threadIdx.x;
    if (idx >= 64 * 1024 * 80) return;
    int d = idx % 80;
    int key = (idx / 80) & 1023;
    int bh = idx / 81920;
    int b = bh >> 5, h = bh & 31;
    float v = qkv[(size_t)(b * 1024 + key) * 7680 + 2560 + h * 80 + d];
    __nv_bfloat16 hh = __float2bfloat16(v);
    size_t o = (size_t)bh * 90112 + key * 88 + d;
    Kh[o] = hh;
    Kl[o] = __float2bfloat16(v - __bfloat162float(hh));
}

// ---------------------------------------------------------------------------
// prep_vt: v part -> transposed bf16 hi/lo [bh][dim][1024]
// grid (16 keytiles of 64, 5 dimtiles, 64 bh), block (16,16), 4 elems/thread
// ---------------------------------------------------------------------------
__global__ void prep_vt(const float* __restrict__ qkv,
                        __nv_bfloat16* __restrict__ Vh,
                        __nv_bfloat16* __restrict__ Vl) {
    __shared__ float t[64][17];
    int kt = blockIdx.x, dt = blockIdx.y, bh = blockIdx.z;
    int b = bh >> 5, h = bh & 31;
    int tx = threadIdx.x, ty = threadIdx.y;
#pragma unroll
    for (int j = 0; j < 4; j++) {
        int key = kt * 64 + ty + j * 16;
        t[ty + j * 16][tx] = qkv[(size_t)(b * 1024 + key) * 7680 + 5120 +
                                 h * 80 + dt * 16 + tx];
    }
    __syncthreads();
    size_t ob = ((size_t)bh * 80 + dt * 16 + ty) * 1024 + kt * 64;
#pragma unroll
    for (int j = 0; j < 4; j++) {
        float v = t[tx + j * 16][ty];
        __nv_bfloat16 hh = __float2bfloat16(v);
        Vh[ob + tx + j * 16] = hh;
        Vl[ob + tx + j * 16] = __float2bfloat16(v - __bfloat162float(hh));
    }
}

// ---------------------------------------------------------------------------
// mma.sync bf16x3 GEMM: C(2048,N) = A @ B^T + bias
// CTA 128x128, 8 warps of 32x64, K chunks of 64, 3-stage cp.async pipeline.
// Stage (64KB): Ah 16K | Al 16K | Bh 16K | Bl 16K. 3 stages = 192KB.
// MMA schedule is term-major to break accumulator RAW chains.
// ---------------------------------------------------------------------------
__global__ __launch_bounds__(256, 1) void gemm_bf16x3(
    const __nv_bfloat16* __restrict__ Ah, const __nv_bfloat16* __restrict__ Al,
    const __nv_bfloat16* __restrict__ Bh, const __nv_bfloat16* __restrict__ Bl,
    const float* __restrict__ bias, float* __restrict__ C, int N) {
    extern __shared__ __align__(1024) char dsm[];
    const uint32_t base = smem_u32(dsm);

    const int tid = threadIdx.x;
    const int wid = tid >> 5, lane = tid & 31;
    const int mw = wid & 3;
    const int nw = wid >> 2;
    const int mt = blockIdx.y, nt = blockIdx.x;
    const int K = 2560;

    const int trow = tid >> 3;
    const int tkg = tid & 7;

    float acc[2][8][4];
#pragma unroll
    for (int a = 0; a < 2; a++)
#pragma unroll
        for (int b = 0; b < 8; b++)
#pragma unroll
            for (int c = 0; c < 4; c++) acc[a][b][c] = 0.0f;

    auto load_chunk = [&](int c, int st) {
        const int k0 = c * 64;
        const uint32_t s0 = base + st * 65536;
#pragma unroll
        for (int j = 0; j < 4; j++) {
            const int row = j * 32 + trow;
            const uint32_t so = SWZ(row * 128 + tkg * 16);
            const __nv_bfloat16* ga = Ah + (size_t)(mt * 128 + row) * K + k0 + tkg * 8;
            const __nv_bfloat16* gal = Al + (size_t)(mt * 128 + row) * K + k0 + tkg * 8;
            const __nv_bfloat16* gb = Bh + (size_t)(nt * 128 + row) * K + k0 + tkg * 8;
            const __nv_bfloat16* gbl = Bl + (size_t)(nt * 128 + row) * K + k0 + tkg * 8;
            CP16(s0 + so, ga);
            CP16(s0 + 16384 + so, gal);
            CP16(s0 + 32768 + so, gb);
            CP16(s0 + 49152 + so, gbl);
        }
        asm volatile("cp.async.commit_group;");
    };

    const int lr = lane & 15;
    const int lc = (lane >> 4) * 16;

    load_chunk(0, 0);
    load_chunk(1, 1);

    int st = 0;
    for (int c = 0; c < 40; c++) {
        if (c < 39) {
            asm volatile("cp.async.wait_group 1;");
        } else {
            asm volatile("cp.async.wait_group 0;");
        }
        __syncthreads();
        if (c + 2 < 40) {
            int st2 = st + 2;
            if (st2 >= 3) st2 -= 3;
            load_chunk(c + 2, st2);
        }

        const uint32_t sA = base + st * 65536;
#pragma unroll
        for (int ks = 0; ks < 4; ks++) {
            uint32_t ah[2][4], al[2][4];
#pragma unroll
            for (int mb = 0; mb < 2; mb++) {
                const uint32_t ro = (mw * 32 + mb * 16 + lr) * 128 + ks * 32 + lc;
                LDSM4(ah[mb], sA + SWZ(ro));
                LDSM4(al[mb], sA + 16384 + SWZ(ro));
            }
            uint32_t bh[4][4], bl[4][4];
#pragma unroll
            for (int nb = 0; nb < 4; nb++) {
                const uint32_t ro = (nw * 64 + nb * 16 + lr) * 128 + ks * 32 + lc;
                LDSM4(bh[nb], sA + 32768 + SWZ(ro));
                LDSM4(bl[nb], sA + 49152 + SWZ(ro));
            }
            // term-major schedule: acc reuse distance = 16 MMAs
#pragma unroll
            for (int mb = 0; mb < 2; mb++)
#pragma unroll
                for (int nb = 0; nb < 4; nb++) {
                    MMA_BF16(acc[mb][nb * 2],     ah[mb], bh[nb][0], bh[nb][2]);
                    MMA_BF16(acc[mb][nb * 2 + 1], ah[mb], bh[nb][1], bh[nb][3]);
                }
#pragma unroll
            for (int mb = 0; mb < 2; mb++)
#pragma unroll
                for (int nb = 0; nb < 4; nb++) {
                    MMA_BF16(acc[mb][nb * 2],     ah[mb], bl[nb][0], bl[nb][2]);
                    MMA_BF16(acc[mb][nb * 2 + 1], ah[mb], bl[nb][1], bl[nb][3]);
                }
#pragma unroll
            for (int mb = 0; mb < 2; mb++)
#pragma unroll
                for (int nb = 0; nb < 4; nb++) {
                    MMA_BF16(acc[mb][nb * 2],     al[mb], bh[nb][0], bh[nb][2]);
                    MMA_BF16(acc[mb][nb * 2 + 1], al[mb], bh[nb][1], bh[nb][3]);
                }
        }
        st++;
        if (st >= 3) st -= 3;
    }

    const int row0 = mt * 128 + mw * 32 + (lane >> 2);
    const int col0 = nt * 128 + nw * 64 + 2 * (lane & 3);
#pragma unroll
    for (int mb = 0; mb < 2; mb++) {
#pragma unroll
        for (int n8 = 0; n8 < 8; n8++) {
            const int gc = col0 + n8 * 8;
            const float b0 = bias[gc], b1 = bias[gc + 1];
            const int r = row0 + mb * 16;
            float2 o0 = make_float2(acc[mb][n8][0] + b0, acc[mb][n8][1] + b1);
            float2 o1 = make_float2(acc[mb][n8][2] + b0, acc[mb][n8][3] + b1);
            *(float2*)&C[(size_t)r * N + gc] = o0;
            *(float2*)&C[(size_t)(r + 8) * N + gc] = o1;
        }
    }
}

// ---------------------------------------------------------------------------
// attn_mma: tensor-core quantum attention (term-major MMA schedules).
// ---------------------------------------------------------------------------
#define A_OFF_QH 0u
#define A_OFF_QL 11264u
#define A_OFF_KH 22528u
#define A_OFF_KL 45056u
#define A_OFF_SCR 67584u
#define A_OFF_SC 101376u
#define A_OFF_PH 0u
#define A_OFF_PL 33024u
#define A_OFF_V 67584u
#define A_OFF_RED 154624u
#define A_SMEM 197632

__global__ __launch_bounds__(256, 1) void attn_mma(
    const float* __restrict__ qkv,
    const __nv_bfloat16* __restrict__ Kh, const __nv_bfloat16* __restrict__ Kl,
    const __nv_bfloat16* __restrict__ Vh, const __nv_bfloat16* __restrict__ Vl,
    const float* __restrict__ gm, const float* __restrict__ gp,
    const float* __restrict__ ga, const float* __restrict__ qp,
    const float* __restrict__ isr,
    __nv_bfloat16* __restrict__ out_hi, __nv_bfloat16* __restrict__ out_lo) {
    extern __shared__ __align__(128) char smc[];
    __shared__ float coeff[240];
    __shared__ float row_l[16];
    char* sm = smc;
    const uint32_t base = smem_u32(smc);

    const int tid = threadIdx.x;
    const int wid = tid >> 5, lane = tid & 31;
    const int lr = lane & 15, lc = (lane >> 4) << 4;
    const int rr = lane >> 2, cc = (lane & 3) * 2;
    const int bh = blockIdx.y, b = bh >> 5, h = bh & 31;
    const int q0 = blockIdx.x * 16;

    if (tid < 240) {
        int g = tid / 80, d = tid - g * 80;
        float r0 = gm[g * 4 + 0] + gm[g * 4 + 1];
        float r1 = gm[g * 4 + 2] + gm[g * 4 + 3];
        float ph = gp[g * 80 + d];
        coeff[tid] = (cosf(ph) * r0 + sinf(ph) * r1) * ga[g * 80 + d];
    }
    __syncthreads();

    const float scale = rsqrtf(80.0f);
    for (int idx = tid; idx < 1280; idx += 256) {
        int r = idx / 80, d = idx - r * 80;
        float v = qkv[(size_t)(b * 1024 + q0 + r) * 7680 + h * 80 + d] * scale;
        float vv[4] = {v, v * coeff[d], v * coeff[80 + d], v * coeff[160 + d]};
#pragma unroll
        for (int g = 0; g < 4; g++) {
            uint32_t o = (g * 16 + r) * 176 + d * 2;
            __nv_bfloat16 hh = __float2bfloat16(vv[g]);
            *(__nv_bfloat16*)(sm + A_OFF_QH + o) = hh;
            *(__nv_bfloat16*)(sm + A_OFF_QL + o) =
                __float2bfloat16(vv[g] - __bfloat162float(hh));
        }
    }

    const __nv_bfloat16* KhB = Kh + (size_t)bh * 90112;
    const __nv_bfloat16* KlB = Kl + (size_t)bh * 90112;
    auto load_k = [&](int kt) {
#pragma unroll
        for (int j = 0; j < 11; j++) {
            int idx = tid + j * 256;
            int m = idx >= 1408;
            int rem = m ? idx - 1408 : idx;
            int row = rem / 11, ch = rem - row * 11;
            const __nv_bfloat16* g =
                (m ? KlB : KhB) + (size_t)(kt * 128 + row) * 88 + ch * 8;
            CP16(base + (m ? A_OFF_KL : A_OFF_KH) + row * 176 + ch * 16, g);
        }
        asm volatile("cp.async.commit_group;");
    };

    load_k(0);
    const float intf = isr[0] * (1.0f / 3.0f);

    const int vr = wid & 3, nh = wid >> 2;
    float* scrv = (float*)(sm + A_OFF_SCR) + vr * 2112;
    float* sc = (float*)(sm + A_OFF_SC);

    // ---- Phase 1: scores ----
    for (int kt = 0; kt < 8; kt++) {
        asm volatile("cp.async.wait_group 0;");
        __syncthreads();

        float acc[8][4];
#pragma unroll
        for (int i = 0; i < 8; i++)
#pragma unroll
            for (int j = 0; j < 4; j++) acc[i][j] = 0.0f;

#pragma unroll
        for (int ks = 0; ks < 5; ks++) {
            uint32_t aH[4], aL[4];
            uint32_t ro = (vr * 16 + lr) * 176 + ks * 32 + lc;
            LDSM4(aH, base + A_OFF_QH + ro);
            LDSM4(aL, base + A_OFF_QL + ro);
            uint32_t bH[4][4], bL[4][4];
#pragma unroll
            for (int nb = 0; nb < 4; nb++) {
                uint32_t rb = (nh * 64 + nb * 16 + lr) * 176 + ks * 32 + lc;
                LDSM4(bH[nb], base + A_OFF_KH + rb);
                LDSM4(bL[nb], base + A_OFF_KL + rb);
            }
#pragma unroll
            for (int nb = 0; nb < 4; nb++) {
                MMA_BF16(acc[nb * 2],     aH, bH[nb][0], bH[nb][2]);
                MMA_BF16(acc[nb * 2 + 1], aH, bH[nb][1], bH[nb][3]);
            }
#pragma unroll
            for (int nb = 0; nb < 4; nb++) {
                MMA_BF16(acc[nb * 2],     aH, bL[nb][0], bL[nb][2]);
                MMA_BF16(acc[nb * 2 + 1], aH, bL[nb][1], bL[nb][3]);
            }
#pragma unroll
            for (int nb = 0; nb < 4; nb++) {
                MMA_BF16(acc[nb * 2],     aL, bH[nb][0], bH[nb][2]);
                MMA_BF16(acc[nb * 2 + 1], aL, bH[nb][1], bH[nb][3]);
            }
        }
#pragma unroll
        for (int n8 = 0; n8 < 8; n8++) {
            int c = nh * 64 + n8 * 8 + cc;
            scrv[rr * 132 + c]           = acc[n8][0];
            scrv[rr * 132 + c + 1]       = acc[n8][1];
            scrv[(rr + 8) * 132 + c]     = acc[n8][2];
            scrv[(rr + 8) * 132 + c + 1] = acc[n8][3];
        }
        __syncthreads();
        if (kt < 7) load_k(kt + 1);

        const float* s0 = (const float*)(sm + A_OFF_SCR);
#pragma unroll
        for (int j = 0; j < 8; j++) {
            int idx = tid + j * 256;
            int r = idx >> 7, c = idx & 127;
            float s  = s0[r * 132 + c];
            float a0 = s0[2112 + r * 132 + c];
            float a1 = s0[4224 + r * 132 + c];
            float a2 = s0[6336 + r * 132 + c];
            sc[r * 1032 + kt * 128 + c] = s + (a0 * a1 + a0 * a2 + a1 * a2) * intf;
        }
        __syncthreads();
    }

    // ---- Phase 2: softmax -> P (bf16 hi/lo) ----
#pragma unroll
    for (int t2 = 0; t2 < 2; t2++) {
        int r = wid * 2 + t2;
        const float* row = sc + r * 1032;
        float mx = -1e30f;
#pragma unroll 8
        for (int j = 0; j < 32; j++) mx = fmaxf(mx, row[lane + j * 32]);
#pragma unroll
        for (int off = 16; off > 0; off >>= 1)
            mx = fmaxf(mx, __shfl_xor_sync(0xffffffffu, mx, off));
        float sum = 0.0f;
#pragma unroll 8
        for (int j = 0; j < 32; j++) {
            int c = lane + j * 32;
            float p = __expf(row[c] - mx);
            sum += p;
            __nv_bfloat16 hh = __float2bfloat16(p);
            *(__nv_bfloat16*)(sm + A_OFF_PH + r * 2064 + c * 2) = hh;
            *(__nv_bfloat16*)(sm + A_OFF_PL + r * 2064 + c * 2) =
                __float2bfloat16(p - __bfloat162float(hh));
        }
#pragma unroll
        for (int off = 16; off > 0; off >>= 1)
            sum += __shfl_xor_sync(0xffffffffu, sum, off);
        if (lane == 0) row_l[r] = sum;
    }
    __syncthreads();

    // ---- Phase 3: P @ V ----
    const __nv_bfloat16* VhB = Vh + (size_t)bh * 81920;
    const __nv_bfloat16* VlB = Vl + (size_t)bh * 81920;
    auto load_v = [&](int kt, int stg) {
#pragma unroll
        for (int j = 0; j < 10; j++) {
            int idx = tid + j * 256;
            int m = idx >= 1280;
            int rem = m ? idx - 1280 : idx;
            int dim = rem >> 4, ch = rem & 15;
            const __nv_bfloat16* g =
                (m ? VlB : VhB) + (size_t)dim * 1024 + kt * 128 + ch * 8;
            CP16(base + A_OFF_V + stg * 43520 + m * 21760 + dim * 272 + ch * 16, g);
        }
        asm volatile("cp.async.commit_group;");
    };

    load_v(0, 0);
    float acc[10][4];
#pragma unroll
    for (int i = 0; i < 10; i++)
#pragma unroll
        for (int j = 0; j < 4; j++) acc[i][j] = 0.0f;

    for (int kt = 0; kt < 8; kt++) {
        const int stg = kt & 1;
        if (kt < 7) {
            load_v(kt + 1, stg ^ 1);
            asm volatile("cp.async.wait_group 1;");
        } else {
            asm volatile("cp.async.wait_group 0;");
        }
        __syncthreads();

        uint32_t aH[4], aL[4];
        uint32_t ro = lr * 2064 + kt * 256 + wid * 32 + lc;
        LDSM4(aH, base + A_OFF_PH + ro);
        LDSM4(aL, base + A_OFF_PL + ro);
        uint32_t bH[5][4], bL[5][4];
#pragma unroll
        for (int nd = 0; nd < 5; nd++) {
            uint32_t rb = stg * 43520 + (nd * 16 + lr) * 272 + wid * 32 + lc;
            LDSM4(bH[nd], base + A_OFF_V + rb);
            LDSM4(bL[nd], base + A_OFF_V + 21760 + rb);
        }
#pragma unroll
        for (int nd = 0; nd < 5; nd++) {
            MMA_BF16(acc[nd * 2],     aH, bH[nd][0], bH[nd][2]);
            MMA_BF16(acc[nd * 2 + 1], aH, bH[nd][1], bH[nd][3]);
        }
#pragma unroll
        for (int nd = 0; nd < 5; nd++) {
            MMA_BF16(acc[nd * 2],     aH, bL[nd][0], bL[nd][2]);
            MMA_BF16(acc[nd * 2 + 1], aH, bL[nd][1], bL[nd][3]);
        }
#pragma unroll
        for (int nd = 0; nd < 5; nd++) {
            MMA_BF16(acc[nd * 2],     aL, bH[nd][0], bH[nd][2]);
            MMA_BF16(acc[nd * 2 + 1], aL, bH[nd][1], bH[nd][3]);
        }
        __syncthreads();
    }

    float* red = (float*)(sm + A_OFF_RED);
    float* redw = red + wid * 1344;
#pragma unroll
    for (int j = 0; j < 10; j++) {
        int d = (j >> 1) * 16 + (j & 1) * 8 + cc;
        redw[rr * 84 + d]           = acc[j][0];
        redw[rr * 84 + d + 1]       = acc[j][1];
        redw[(rr + 8) * 84 + d]     = acc[j][2];
        redw[(rr + 8) * 84 + d + 1] = acc[j][3];
    }
    __syncthreads();

    const float cph = cosf(qp[h]);
    for (int idx = tid; idx < 1280; idx += 256) {
        int r = idx / 80, d = idx - r * 80;
        float s = 0.0f;
#pragma unroll
        for (int w = 0; w < 8; w++) s += red[w * 1344 + r * 84 + d];
        float o = s * cph / row_l[r];
        size_t go = (size_t)(b * 1024 + q0 + r) * 2560 + h * 80 + d;
        __nv_bfloat16 hh = __float2bfloat16(o);
        out_hi[go] = hh;
        out_lo[go] = __float2bfloat16(o - __bfloat162float(hh));
    }
}

// ---------------------------------------------------------------------------
extern "C" void kernel_launch(void* const* d_in, const int* in_sizes, int n_in,
                              void* d_out, int out_size) {
    const float* hidden = (const float*)d_in[0];
    const float* Wqkv   = (const float*)d_in[1];
    const float* bqkv   = (const float*)d_in[2];
    const float* Wproj  = (const float*)d_in[3];
    const float* bproj  = (const float*)d_in[4];
    const float* gm     = (const float*)d_in[5];
    const float* gp     = (const float*)d_in[6];
    const float* ga     = (const float*)d_in[7];
    const float* qp     = (const float*)d_in[8];
    const float* isr    = (const float*)d_in[9];
    float* out = (float*)d_out;

    void *p_qkv, *p_hh, *p_hl, *p_wqh, *p_wql, *p_wph, *p_wpl, *p_ah, *p_al;
    void *p_kh, *p_kl, *p_vh, *p_vl;
    cudaGetSymbolAddress(&p_qkv, g_qkv);
    cudaGetSymbolAddress(&p_hh, g_hid_hi);
    cudaGetSymbolAddress(&p_hl, g_hid_lo);
    cudaGetSymbolAddress(&p_wqh, g_wqkvT_hi);
    cudaGetSymbolAddress(&p_wql, g_wqkvT_lo);
    cudaGetSymbolAddress(&p_wph, g_wprojT_hi);
    cudaGetSymbolAddress(&p_wpl, g_wprojT_lo);
    cudaGetSymbolAddress(&p_ah, g_attn_hi);
    cudaGetSymbolAddress(&p_al, g_attn_lo);
    cudaGetSymbolAddress(&p_kh, g_Khi);
    cudaGetSymbolAddress(&p_kl, g_Klo);
    cudaGetSymbolAddress(&p_vh, g_Vthi);
    cudaGetSymbolAddress(&p_vl, g_Vtlo);

    const int GEMM_SMEM = 3 * 65536;
    cudaFuncSetAttribute(gemm_bf16x3,
                         cudaFuncAttributeMaxDynamicSharedMemorySize, GEMM_SMEM);
    cudaFuncSetAttribute(attn_mma,
                         cudaFuncAttributeMaxDynamicSharedMemorySize, A_SMEM);

    // 1) input conversions
    conv_hilo<<<5120, 256>>>(hidden, (__nv_bfloat16*)p_hh, (__nv_bfloat16*)p_hl,
                             2048 * 2560 / 4);
    transpose_conv<<<dim3(7680 / 32, 2560 / 32), dim3(32, 8)>>>(
        Wqkv, (__nv_bfloat16*)p_wqh, (__nv_bfloat16*)p_wql, 2560, 7680);
    transpose_conv<<<dim3(2560 / 32, 2560 / 32), dim3(32, 8)>>>(
        Wproj, (__nv_bfloat16*)p_wph, (__nv_bfloat16*)p_wpl, 2560, 2560);

    // 2) qkv = hidden @ Wqkv + bqkv
    gemm_bf16x3<<<dim3(60, 16), 256, GEMM_SMEM>>>(
        (const __nv_bfloat16*)p_hh, (const __nv_bfloat16*)p_hl,
        (const __nv_bfloat16*)p_wqh, (const __nv_bfloat16*)p_wql,
        bqkv, (float*)p_qkv, 7680);

    // 3) K/V conversion for tensor-core attention
    prep_k<<<20480, 256>>>((const float*)p_qkv, (__nv_bfloat16*)p_kh,
                           (__nv_bfloat16*)p_kl);
    prep_vt<<<dim3(16, 5, 64), dim3(16, 16)>>>(
        (const float*)p_qkv, (__nv_bfloat16*)p_vh, (__nv_bfloat16*)p_vl);

    // 4) tensor-core quantum attention -> bf16 hi/lo
    attn_mma<<<dim3(64, 64), 256, A_SMEM>>>(
        (const float*)p_qkv,
        (const __nv_bfloat16*)p_kh, (const __nv_bfloat16*)p_kl,
        (const __nv_bfloat16*)p_vh, (const __nv_bfloat16*)p_vl,
        gm, gp, ga, qp, isr,
        (__nv_bfloat16*)p_ah, (__nv_bfloat16*)p_al);

    // 5) out = attn @ Wproj + bproj
    gemm_bf16x3<<<dim3(20, 16), 256, GEMM_SMEM>>>(
        (const __nv_bfloat16*)p_ah, (const __nv_bfloat16*)p_al,
        (const __nv_bfloat16*)p_wph, (const __nv_bfloat16*)p_wpl,
        bproj, out, 2560);
}

// round 6
// speedup vs baseline: 3.0552x; 1.0602x over previous
#include <cuda_runtime.h>
#include <cuda_bf16.h>
#include <stdint.h>
#include <math.h>

// Problem constants: B=2, S=1024, E=2560, H=32, D=80, 3E=7680, BS=2048, K=2560

// ---------------- device scratch ----------------
__device__ float g_qkv[2048ull * 7680];
__device__ __nv_bfloat16 g_hid_hi[2048ull * 2560];
__device__ __nv_bfloat16 g_hid_lo[2048ull * 2560];
__device__ __nv_bfloat16 g_wqkvT_hi[7680ull * 2560];   // (N,K)
__device__ __nv_bfloat16 g_wqkvT_lo[7680ull * 2560];
__device__ __nv_bfloat16 g_wprojT_hi[2560ull * 2560];
__device__ __nv_bfloat16 g_wprojT_lo[2560ull * 2560];
__device__ __nv_bfloat16 g_attn_hi[2048ull * 2560];
__device__ __nv_bfloat16 g_attn_lo[2048ull * 2560];
__device__ __nv_bfloat16 g_Khi[64ull * 1024 * 88];     // [bh][key][88]
__device__ __nv_bfloat16 g_Klo[64ull * 1024 * 88];
__device__ __nv_bfloat16 g_Vthi[64ull * 80 * 1024];    // [bh][dim][1024]
__device__ __nv_bfloat16 g_Vtlo[64ull * 80 * 1024];

__device__ __forceinline__ uint32_t smem_u32(const void* p) {
    uint32_t a;
    asm("{ .reg .u64 t; cvta.to.shared.u64 t, %1; cvt.u32.u64 %0, t; }"
        : "=r"(a) : "l"(p));
    return a;
}

#define SWZ(o) ((uint32_t)(o) ^ ((((uint32_t)(o)) >> 3) & 0x70u))

#define CP16(s, g) \
    asm volatile("cp.async.cg.shared.global [%0], [%1], 16;" :: "r"(s), "l"(g))

#define LDSM4(r, addr) \
    asm volatile("ldmatrix.sync.aligned.m8n8.x4.shared.b16 {%0,%1,%2,%3}, [%4];" \
                 : "=r"((r)[0]), "=r"((r)[1]), "=r"((r)[2]), "=r"((r)[3]) \
                 : "r"(addr))

#define MMA_BF16(acc, A, b0, b1) \
    asm volatile("mma.sync.aligned.m16n8k16.row.col.f32.bf16.bf16.f32 " \
                 "{%0,%1,%2,%3}, {%4,%5,%6,%7}, {%8,%9}, {%0,%1,%2,%3};" \
                 : "+f"((acc)[0]), "+f"((acc)[1]), "+f"((acc)[2]), "+f"((acc)[3]) \
                 : "r"((A)[0]), "r"((A)[1]), "r"((A)[2]), "r"((A)[3]), \
                   "r"(b0), "r"(b1))

// ---------------------------------------------------------------------------
// Conversion: fp32 -> bf16 hi/lo
// ---------------------------------------------------------------------------
__global__ void conv_hilo(const float* __restrict__ X,
                          __nv_bfloat16* __restrict__ Hh,
                          __nv_bfloat16* __restrict__ Ll, int n4) {
    int i = blockIdx.x * blockDim.x + threadIdx.x;
    if (i >= n4) return;
    float4 v = ((const float4*)X)[i];
    __nv_bfloat16 h0 = __float2bfloat16(v.x), h1 = __float2bfloat16(v.y);
    __nv_bfloat16 h2 = __float2bfloat16(v.z), h3 = __float2bfloat16(v.w);
    __nv_bfloat162 a, b;
    a.x = h0; a.y = h1; b.x = h2; b.y = h3;
    ((__nv_bfloat162*)Hh)[i * 2] = a;
    ((__nv_bfloat162*)Hh)[i * 2 + 1] = b;
    __nv_bfloat162 c, d;
    c.x = __float2bfloat16(v.x - __bfloat162float(h0));
    c.y = __float2bfloat16(v.y - __bfloat162float(h1));
    d.x = __float2bfloat16(v.z - __bfloat162float(h2));
    d.y = __float2bfloat16(v.w - __bfloat162float(h3));
    ((__nv_bfloat162*)Ll)[i * 2] = c;
    ((__nv_bfloat162*)Ll)[i * 2 + 1] = d;
}

// ---------------------------------------------------------------------------
// Transpose + convert: W (K,N) fp32 -> Th/Tl (N,K) bf16
// ---------------------------------------------------------------------------
__global__ void transpose_conv(const float* __restrict__ W,
                               __nv_bfloat16* __restrict__ Th,
                               __nv_bfloat16* __restrict__ Tl, int K, int N) {
    __shared__ float t[32][33];
    int n0 = blockIdx.x * 32, k0 = blockIdx.y * 32;
    int tx = threadIdx.x, ty = threadIdx.y;
#pragma unroll
    for (int j = 0; j < 4; j++)
        t[ty + j * 8][tx] = W[(size_t)(k0 + ty + j * 8) * N + n0 + tx];
    __syncthreads();
#pragma unroll
    for (int j = 0; j < 4; j++) {
        float v = t[tx][ty + j * 8];
        __nv_bfloat16 h = __float2bfloat16(v);
        size_t o = (size_t)(n0 + ty + j * 8) * K + k0 + tx;
        Th[o] = h;
        Tl[o] = __float2bfloat16(v - __bfloat162float(h));
    }
}

// ---------------------------------------------------------------------------
// prep_k: k part of qkv -> bf16 hi/lo [bh][key][88]
// ---------------------------------------------------------------------------
__global__ void prep_k(const float* __restrict__ qkv,
                       __nv_bfloat16* __restrict__ Kh,
                       __nv_bfloat16* __restrict__ Kl) {
    int idx = blockIdx.x * 256 + threadIdx.x;
    if (idx >= 64 * 1024 * 80) return;
    int d = idx % 80;
    int key = (idx / 80) & 1023;
    int bh = idx / 81920;
    int b = bh >> 5, h = bh & 31;
    float v = qkv[(size_t)(b * 1024 + key) * 7680 + 2560 + h * 80 + d];
    __nv_bfloat16 hh = __float2bfloat16(v);
    size_t o = (size_t)bh * 90112 + key * 88 + d;
    Kh[o] = hh;
    Kl[o] = __float2bfloat16(v - __bfloat162float(hh));
}

// ---------------------------------------------------------------------------
// prep_vt: v part -> transposed bf16 hi/lo [bh][dim][1024]
// ---------------------------------------------------------------------------
__global__ void prep_vt(const float* __restrict__ qkv,
                        __nv_bfloat16* __restrict__ Vh,
                        __nv_bfloat16* __restrict__ Vl) {
    __shared__ float t[64][17];
    int kt = blockIdx.x, dt = blockIdx.y, bh = blockIdx.z;
    int b = bh >> 5, h = bh & 31;
    int tx = threadIdx.x, ty = threadIdx.y;
#pragma unroll
    for (int j = 0; j < 4; j++) {
        int key = kt * 64 + ty + j * 16;
        t[ty + j * 16][tx] = qkv[(size_t)(b * 1024 + key) * 7680 + 5120 +
                                 h * 80 + dt * 16 + tx];
    }
    __syncthreads();
    size_t ob = ((size_t)bh * 80 + dt * 16 + ty) * 1024 + kt * 64;
#pragma unroll
    for (int j = 0; j < 4; j++) {
        float v = t[tx + j * 16][ty];
        __nv_bfloat16 hh = __float2bfloat16(v);
        Vh[ob + tx + j * 16] = hh;
        Vl[ob + tx + j * 16] = __float2bfloat16(v - __bfloat162float(hh));
    }
}

// ---------------------------------------------------------------------------
// mma.sync bf16x3 GEMM: C(2048,N) = A @ B^T + bias
// CTA 128x128, 512 threads (16 warps, warp tile 32x32 -> 4 warps/SMSP),
// K chunks of 64, 3-stage cp.async pipeline (192KB smem).
// ---------------------------------------------------------------------------
__global__ __launch_bounds__(512, 1) void gemm_bf16x3(
    const __nv_bfloat16* __restrict__ Ah, const __nv_bfloat16* __restrict__ Al,
    const __nv_bfloat16* __restrict__ Bh, const __nv_bfloat16* __restrict__ Bl,
    const float* __restrict__ bias, float* __restrict__ C, int N) {
    extern __shared__ __align__(1024) char dsm[];
    const uint32_t base = smem_u32(dsm);

    const int tid = threadIdx.x;
    const int wid = tid >> 5, lane = tid & 31;
    const int mw = wid & 3;       // 4 x 32 rows
    const int nw = wid >> 2;      // 4 x 32 cols
    const int mt = blockIdx.y, nt = blockIdx.x;
    const int K = 2560;

    const int trow = tid >> 3;    // 0..63
    const int tkg = tid & 7;

    float acc[2][4][4];
#pragma unroll
    for (int a = 0; a < 2; a++)
#pragma unroll
        for (int b = 0; b < 4; b++)
#pragma unroll
            for (int c = 0; c < 4; c++) acc[a][b][c] = 0.0f;

    auto load_chunk = [&](int c, int st) {
        const int k0 = c * 64;
        const uint32_t s0 = base + st * 65536;
#pragma unroll
        for (int j = 0; j < 2; j++) {
            const int row = j * 64 + trow;
            const uint32_t so = SWZ(row * 128 + tkg * 16);
            const __nv_bfloat16* ga = Ah + (size_t)(mt * 128 + row) * K + k0 + tkg * 8;
            const __nv_bfloat16* gal = Al + (size_t)(mt * 128 + row) * K + k0 + tkg * 8;
            const __nv_bfloat16* gb = Bh + (size_t)(nt * 128 + row) * K + k0 + tkg * 8;
            const __nv_bfloat16* gbl = Bl + (size_t)(nt * 128 + row) * K + k0 + tkg * 8;
            CP16(s0 + so, ga);
            CP16(s0 + 16384 + so, gal);
            CP16(s0 + 32768 + so, gb);
            CP16(s0 + 49152 + so, gbl);
        }
        asm volatile("cp.async.commit_group;");
    };

    const int lr = lane & 15;
    const int lc = (lane >> 4) * 16;

    load_chunk(0, 0);
    load_chunk(1, 1);

    int st = 0;
    for (int c = 0; c < 40; c++) {
        if (c < 39) {
            asm volatile("cp.async.wait_group 1;");
        } else {
            asm volatile("cp.async.wait_group 0;");
        }
        __syncthreads();
        if (c + 2 < 40) {
            int st2 = st + 2;
            if (st2 >= 3) st2 -= 3;
            load_chunk(c + 2, st2);
        }

        const uint32_t sA = base + st * 65536;
#pragma unroll
        for (int ks = 0; ks < 4; ks++) {
            uint32_t ah[2][4], al[2][4];
#pragma unroll
            for (int mb = 0; mb < 2; mb++) {
                const uint32_t ro = (mw * 32 + mb * 16 + lr) * 128 + ks * 32 + lc;
                LDSM4(ah[mb], sA + SWZ(ro));
                LDSM4(al[mb], sA + 16384 + SWZ(ro));
            }
            uint32_t bh2[2][4], bl2[2][4];
#pragma unroll
            for (int nb = 0; nb < 2; nb++) {
                const uint32_t ro = (nw * 32 + nb * 16 + lr) * 128 + ks * 32 + lc;
                LDSM4(bh2[nb], sA + 32768 + SWZ(ro));
                LDSM4(bl2[nb], sA + 49152 + SWZ(ro));
            }
            // term-major: acc reuse distance = 8 MMAs
#pragma unroll
            for (int mb = 0; mb < 2; mb++)
#pragma unroll
                for (int nb = 0; nb < 2; nb++) {
                    MMA_BF16(acc[mb][nb * 2],     ah[mb], bh2[nb][0], bh2[nb][2]);
                    MMA_BF16(acc[mb][nb * 2 + 1], ah[mb], bh2[nb][1], bh2[nb][3]);
                }
#pragma unroll
            for (int mb = 0; mb < 2; mb++)
#pragma unroll
                for (int nb = 0; nb < 2; nb++) {
                    MMA_BF16(acc[mb][nb * 2],     ah[mb], bl2[nb][0], bl2[nb][2]);
                    MMA_BF16(acc[mb][nb * 2 + 1], ah[mb], bl2[nb][1], bl2[nb][3]);
                }
#pragma unroll
            for (int mb = 0; mb < 2; mb++)
#pragma unroll
                for (int nb = 0; nb < 2; nb++) {
                    MMA_BF16(acc[mb][nb * 2],     al[mb], bh2[nb][0], bh2[nb][2]);
                    MMA_BF16(acc[mb][nb * 2 + 1], al[mb], bh2[nb][1], bh2[nb][3]);
                }
        }
        st++;
        if (st >= 3) st -= 3;
    }

    const int row0 = mt * 128 + mw * 32 + (lane >> 2);
    const int col0 = nt * 128 + nw * 32 + 2 * (lane & 3);
#pragma unroll
    for (int mb = 0; mb < 2; mb++) {
#pragma unroll
        for (int n8 = 0; n8 < 4; n8++) {
            const int gc = col0 + n8 * 8;
            const float b0 = bias[gc], b1 = bias[gc + 1];
            const int r = row0 + mb * 16;
            float2 o0 = make_float2(acc[mb][n8][0] + b0, acc[mb][n8][1] + b1);
            float2 o1 = make_float2(acc[mb][n8][2] + b0, acc[mb][n8][3] + b1);
            *(float2*)&C[(size_t)r * N + gc] = o0;
            *(float2*)&C[(size_t)(r + 8) * N + gc] = o1;
        }
    }
}

// ---------------------------------------------------------------------------
// attn_mma v2: warp = 16-key slice, all 4 variants in registers.
// smem (bytes):
//  ph1:  QH 0..11264 | QL ..22528 | K 22528..112640 (2 stages x (KH 22528 + KL 22528))
//        SC 112640..178688 (16 x 1032 fp32)
//  ph23: PH 0..33024 | PL ..66048 | V 67584..154624 | RED 154624..197632
// ---------------------------------------------------------------------------
#define A_OFF_QH 0u
#define A_OFF_QL 11264u
#define A_OFF_K  22528u
#define A_K_STG  45056u
#define A_OFF_SC 112640u
#define A_OFF_PH 0u
#define A_OFF_PL 33024u
#define A_OFF_V 67584u
#define A_OFF_RED 154624u
#define A_SMEM 197632

__global__ __launch_bounds__(256, 1) void attn_mma(
    const float* __restrict__ qkv,
    const __nv_bfloat16* __restrict__ Kh, const __nv_bfloat16* __restrict__ Kl,
    const __nv_bfloat16* __restrict__ Vh, const __nv_bfloat16* __restrict__ Vl,
    const float* __restrict__ gm, const float* __restrict__ gp,
    const float* __restrict__ ga, const float* __restrict__ qp,
    const float* __restrict__ isr,
    __nv_bfloat16* __restrict__ out_hi, __nv_bfloat16* __restrict__ out_lo) {
    extern __shared__ __align__(128) char smc[];
    __shared__ float coeff[240];
    __shared__ float row_l[16];
    char* sm = smc;
    const uint32_t base = smem_u32(smc);

    const int tid = threadIdx.x;
    const int wid = tid >> 5, lane = tid & 31;
    const int lr = lane & 15, lc = (lane >> 4) << 4;
    const int rr = lane >> 2, cc = (lane & 3) * 2;
    const int bh = blockIdx.y, b = bh >> 5, h = bh & 31;
    const int q0 = blockIdx.x * 16;

    const __nv_bfloat16* KhB = Kh + (size_t)bh * 90112;
    const __nv_bfloat16* KlB = Kl + (size_t)bh * 90112;
    auto load_k = [&](int kt, int stg) {
        const uint32_t sb = base + A_OFF_K + (uint32_t)stg * A_K_STG;
#pragma unroll
        for (int j = 0; j < 11; j++) {
            int idx = tid + j * 256;
            int m = idx >= 1408;
            int rem = m ? idx - 1408 : idx;
            int row = rem / 11, ch = rem - row * 11;
            const __nv_bfloat16* g =
                (m ? KlB : KhB) + (size_t)(kt * 128 + row) * 88 + ch * 8;
            CP16(sb + m * 22528u + row * 176 + ch * 16, g);
        }
        asm volatile("cp.async.commit_group;");
    };

    load_k(0, 0);

    if (tid < 240) {
        int g = tid / 80, d = tid - g * 80;
        float r0 = gm[g * 4 + 0] + gm[g * 4 + 1];
        float r1 = gm[g * 4 + 2] + gm[g * 4 + 3];
        float ph = gp[g * 80 + d];
        coeff[tid] = (cosf(ph) * r0 + sinf(ph) * r1) * ga[g * 80 + d];
    }
    __syncthreads();

    // build Qext (4 variants x 16 rows x 80 dims, scale folded in)
    const float scale = rsqrtf(80.0f);
    for (int idx = tid; idx < 1280; idx += 256) {
        int r = idx / 80, d = idx - r * 80;
        float v = qkv[(size_t)(b * 1024 + q0 + r) * 7680 + h * 80 + d] * scale;
        float vv[4] = {v, v * coeff[d], v * coeff[80 + d], v * coeff[160 + d]};
#pragma unroll
        for (int g = 0; g < 4; g++) {
            uint32_t o = (g * 16 + r) * 176 + d * 2;
            __nv_bfloat16 hh = __float2bfloat16(vv[g]);
            *(__nv_bfloat16*)(sm + A_OFF_QH + o) = hh;
            *(__nv_bfloat16*)(sm + A_OFF_QL + o) =
                __float2bfloat16(vv[g] - __bfloat162float(hh));
        }
    }

    const float intf = isr[0] * (1.0f / 3.0f);
    float* sc = (float*)(sm + A_OFF_SC);     // 16 x 1032

    // ---- Phase 1: scores; warp wid owns keys [kt*128 + wid*16, +16) ----
    for (int kt = 0; kt < 8; kt++) {
        const int stg = kt & 1;
        asm volatile("cp.async.wait_group 0;");
        __syncthreads();                      // K(stg) visible; prev reads done
        if (kt < 7) load_k(kt + 1, stg ^ 1);  // overlap with compute

        const uint32_t kbase = base + A_OFF_K + (uint32_t)stg * A_K_STG;
        float acc[4][2][4];
#pragma unroll
        for (int g = 0; g < 4; g++)
#pragma unroll
            for (int i = 0; i < 2; i++)
#pragma unroll
                for (int j = 0; j < 4; j++) acc[g][i][j] = 0.0f;

#pragma unroll
        for (int ks = 0; ks < 5; ks++) {
            uint32_t aH[4][4], aL[4][4];
#pragma unroll
            for (int g = 0; g < 4; g++) {
                uint32_t ro = (g * 16 + lr) * 176 + ks * 32 + lc;
                LDSM4(aH[g], base + A_OFF_QH + ro);
                LDSM4(aL[g], base + A_OFF_QL + ro);
            }
            uint32_t bH[4], bL[4];
            uint32_t rb = (wid * 16 + lr) * 176 + ks * 32 + lc;
            LDSM4(bH, kbase + rb);
            LDSM4(bL, kbase + 22528u + rb);
            // term-major, reuse distance 8
#pragma unroll
            for (int g = 0; g < 4; g++) {
                MMA_BF16(acc[g][0], aH[g], bH[0], bH[2]);
                MMA_BF16(acc[g][1], aH[g], bH[1], bH[3]);
            }
#pragma unroll
            for (int g = 0; g < 4; g++) {
                MMA_BF16(acc[g][0], aH[g], bL[0], bL[2]);
                MMA_BF16(acc[g][1], aH[g], bL[1], bL[3]);
            }
#pragma unroll
            for (int g = 0; g < 4; g++) {
                MMA_BF16(acc[g][0], aL[g], bH[0], bH[2]);
                MMA_BF16(acc[g][1], aL[g], bH[1], bH[3]);
            }
        }

        // combine interference in registers, write final fp32 scores
#pragma unroll
        for (int n8 = 0; n8 < 2; n8++) {
#pragma unroll
            for (int j = 0; j < 4; j++) {
                int r = rr + (j >> 1) * 8;
                int c = kt * 128 + wid * 16 + n8 * 8 + cc + (j & 1);
                float s  = acc[0][n8][j];
                float a0 = acc[1][n8][j];
                float a1 = acc[2][n8][j];
                float a2 = acc[3][n8][j];
                sc[r * 1032 + c] = s + (a0 * a1 + a0 * a2 + a1 * a2) * intf;
            }
        }
    }
    __syncthreads();

    // ---- Phase 2: softmax -> P (bf16 hi/lo) ----
#pragma unroll
    for (int t2 = 0; t2 < 2; t2++) {
        int r = wid * 2 + t2;
        const float* row = sc + r * 1032;
        float mx = -1e30f;
#pragma unroll 8
        for (int j = 0; j < 32; j++) mx = fmaxf(mx, row[lane + j * 32]);
#pragma unroll
        for (int off = 16; off > 0; off >>= 1)
            mx = fmaxf(mx, __shfl_xor_sync(0xffffffffu, mx, off));
        float sum = 0.0f;
#pragma unroll 8
        for (int j = 0; j < 32; j++) {
            int c = lane + j * 32;
            float p = __expf(row[c] - mx);
            sum += p;
            __nv_bfloat16 hh = __float2bfloat16(p);
            *(__nv_bfloat16*)(sm + A_OFF_PH + r * 2064 + c * 2) = hh;
            *(__nv_bfloat16*)(sm + A_OFF_PL + r * 2064 + c * 2) =
                __float2bfloat16(p - __bfloat162float(hh));
        }
#pragma unroll
        for (int off = 16; off > 0; off >>= 1)
            sum += __shfl_xor_sync(0xffffffffu, sum, off);
        if (lane == 0) row_l[r] = sum;
    }
    __syncthreads();

    // ---- Phase 3: P @ V ----
    const __nv_bfloat16* VhB = Vh + (size_t)bh * 81920;
    const __nv_bfloat16* VlB = Vl + (size_t)bh * 81920;
    auto load_v = [&](int kt, int stg) {
#pragma unroll
        for (int j = 0; j < 10; j++) {
            int idx = tid + j * 256;
            int m = idx >= 1280;
            int rem = m ? idx - 1280 : idx;
            int dim = rem >> 4, ch = rem & 15;
            const __nv_bfloat16* g =
                (m ? VlB : VhB) + (size_t)dim * 1024 + kt * 128 + ch * 8;
            CP16(base + A_OFF_V + stg * 43520 + m * 21760 + dim * 272 + ch * 16, g);
        }
        asm volatile("cp.async.commit_group;");
    };

    load_v(0, 0);
    float acc[10][4];
#pragma unroll
    for (int i = 0; i < 10; i++)
#pragma unroll
        for (int j = 0; j < 4; j++) acc[i][j] = 0.0f;

    for (int kt = 0; kt < 8; kt++) {
        const int stg = kt & 1;
        if (kt < 7) {
            load_v(kt + 1, stg ^ 1);
            asm volatile("cp.async.wait_group 1;");
        } else {
            asm volatile("cp.async.wait_group 0;");
        }
        __syncthreads();

        uint32_t aH[4], aL[4];
        uint32_t ro = lr * 2064 + kt * 256 + wid * 32 + lc;
        LDSM4(aH, base + A_OFF_PH + ro);
        LDSM4(aL, base + A_OFF_PL + ro);
        uint32_t bH[5][4], bL[5][4];
#pragma unroll
        for (int nd = 0; nd < 5; nd++) {
            uint32_t rb = stg * 43520 + (nd * 16 + lr) * 272 + wid * 32 + lc;
            LDSM4(bH[nd], base + A_OFF_V + rb);
            LDSM4(bL[nd], base + A_OFF_V + 21760 + rb);
        }
#pragma unroll
        for (int nd = 0; nd < 5; nd++) {
            MMA_BF16(acc[nd * 2],     aH, bH[nd][0], bH[nd][2]);
            MMA_BF16(acc[nd * 2 + 1], aH, bH[nd][1], bH[nd][3]);
        }
#pragma unroll
        for (int nd = 0; nd < 5; nd++) {
            MMA_BF16(acc[nd * 2],     aH, bL[nd][0], bL[nd][2]);
            MMA_BF16(acc[nd * 2 + 1], aH, bL[nd][1], bL[nd][3]);
        }
#pragma unroll
        for (int nd = 0; nd < 5; nd++) {
            MMA_BF16(acc[nd * 2],     aL, bH[nd][0], bH[nd][2]);
            MMA_BF16(acc[nd * 2 + 1], aL, bH[nd][1], bH[nd][3]);
        }
        __syncthreads();
    }

    float* red = (float*)(sm + A_OFF_RED);
    float* redw = red + wid * 1344;
#pragma unroll
    for (int j = 0; j < 10; j++) {
        int d = (j >> 1) * 16 + (j & 1) * 8 + cc;
        redw[rr * 84 + d]           = acc[j][0];
        redw[rr * 84 + d + 1]       = acc[j][1];
        redw[(rr + 8) * 84 + d]     = acc[j][2];
        redw[(rr + 8) * 84 + d + 1] = acc[j][3];
    }
    __syncthreads();

    const float cph = cosf(qp[h]);
    for (int idx = tid; idx < 1280; idx += 256) {
        int r = idx / 80, d = idx - r * 80;
        float s = 0.0f;
#pragma unroll
        for (int w = 0; w < 8; w++) s += red[w * 1344 + r * 84 + d];
        float o = s * cph / row_l[r];
        size_t go = (size_t)(b * 1024 + q0 + r) * 2560 + h * 80 + d;
        __nv_bfloat16 hh = __float2bfloat16(o);
        out_hi[go] = hh;
        out_lo[go] = __float2bfloat16(o - __bfloat162float(hh));
    }
}

// ---------------------------------------------------------------------------
extern "C" void kernel_launch(void* const* d_in, const int* in_sizes, int n_in,
                              void* d_out, int out_size) {
    const float* hidden = (const float*)d_in[0];
    const float* Wqkv   = (const float*)d_in[1];
    const float* bqkv   = (const float*)d_in[2];
    const float* Wproj  = (const float*)d_in[3];
    const float* bproj  = (const float*)d_in[4];
    const float* gm     = (const float*)d_in[5];
    const float* gp     = (const float*)d_in[6];
    const float* ga     = (const float*)d_in[7];
    const float* qp     = (const float*)d_in[8];
    const float* isr    = (const float*)d_in[9];
    float* out = (float*)d_out;

    void *p_qkv, *p_hh, *p_hl, *p_wqh, *p_wql, *p_wph, *p_wpl, *p_ah, *p_al;
    void *p_kh, *p_kl, *p_vh, *p_vl;
    cudaGetSymbolAddress(&p_qkv, g_qkv);
    cudaGetSymbolAddress(&p_hh, g_hid_hi);
    cudaGetSymbolAddress(&p_hl, g_hid_lo);
    cudaGetSymbolAddress(&p_wqh, g_wqkvT_hi);
    cudaGetSymbolAddress(&p_wql, g_wqkvT_lo);
    cudaGetSymbolAddress(&p_wph, g_wprojT_hi);
    cudaGetSymbolAddress(&p_wpl, g_wprojT_lo);
    cudaGetSymbolAddress(&p_ah, g_attn_hi);
    cudaGetSymbolAddress(&p_al, g_attn_lo);
    cudaGetSymbolAddress(&p_kh, g_Khi);
    cudaGetSymbolAddress(&p_kl, g_Klo);
    cudaGetSymbolAddress(&p_vh, g_Vthi);
    cudaGetSymbolAddress(&p_vl, g_Vtlo);

    const int GEMM_SMEM = 3 * 65536;
    cudaFuncSetAttribute(gemm_bf16x3,
                         cudaFuncAttributeMaxDynamicSharedMemorySize, GEMM_SMEM);
    cudaFuncSetAttribute(attn_mma,
                         cudaFuncAttributeMaxDynamicSharedMemorySize, A_SMEM);

    // 1) input conversions
    conv_hilo<<<5120, 256>>>(hidden, (__nv_bfloat16*)p_hh, (__nv_bfloat16*)p_hl,
                             2048 * 2560 / 4);
    transpose_conv<<<dim3(7680 / 32, 2560 / 32), dim3(32, 8)>>>(
        Wqkv, (__nv_bfloat16*)p_wqh, (__nv_bfloat16*)p_wql, 2560, 7680);
    transpose_conv<<<dim3(2560 / 32, 2560 / 32), dim3(32, 8)>>>(
        Wproj, (__nv_bfloat16*)p_wph, (__nv_bfloat16*)p_wpl, 2560, 2560);

    // 2) qkv = hidden @ Wqkv + bqkv
    gemm_bf16x3<<<dim3(60, 16), 512, GEMM_SMEM>>>(
        (const __nv_bfloat16*)p_hh, (const __nv_bfloat16*)p_hl,
        (const __nv_bfloat16*)p_wqh, (const __nv_bfloat16*)p_wql,
        bqkv, (float*)p_qkv, 7680);

    // 3) K/V conversion for tensor-core attention
    prep_k<<<20480, 256>>>((const float*)p_qkv, (__nv_bfloat16*)p_kh,
                           (__nv_bfloat16*)p_kl);
    prep_vt<<<dim3(16, 5, 64), dim3(16, 16)>>>(
        (const float*)p_qkv, (__nv_bfloat16*)p_vh, (__nv_bfloat16*)p_vl);

    // 4) tensor-core quantum attention -> bf16 hi/lo
    attn_mma<<<dim3(64, 64), 256, A_SMEM>>>(
        (const float*)p_qkv,
        (const __nv_bfloat16*)p_kh, (const __nv_bfloat16*)p_kl,
        (const __nv_bfloat16*)p_vh, (const __nv_bfloat16*)p_vl,
        gm, gp, ga, qp, isr,
        (__nv_bfloat16*)p_ah, (__nv_bfloat16*)p_al);

    // 5) out = attn @ Wproj + bproj
    gemm_bf16x3<<<dim3(20, 16), 512, GEMM_SMEM>>>(
        (const __nv_bfloat16*)p_ah, (const __nv_bfloat16*)p_al,
        (const __nv_bfloat16*)p_wph, (const __nv_bfloat16*)p_wpl,
        bproj, out, 2560);
}